// round 5
// baseline (speedup 1.0000x reference)
#include <cuda_runtime.h>
#include <cuda_bf16.h>

#define N_NODES 100000
#define N_EDGES 1600000
#define C 64
#define TILE 64
#define HPAD 68   // padded row stride (floats) for h/hn tiles

// ---------------- scratch (device globals: no allocations allowed) ----------------
__device__ __align__(16) float g_h0[N_NODES * C];
__device__ __align__(16) float g_h1[N_NODES * C];
__device__ __align__(16) float g_agg[N_NODES * C];
__device__ __align__(16) float g_ideg[N_NODES];
__device__ int g_cnt[N_NODES];
__device__ int g_row_ptr[N_NODES + 1];
__device__ int g_cursor[N_NODES];
__device__ int g_csr_src[N_EDGES];

// ---------------- CSR build ----------------
__global__ void zero_cnt_kernel(int* __restrict__ cnt) {
    int i = blockIdx.x * blockDim.x + threadIdx.x;
    if (i < N_NODES) cnt[i] = 0;
}

__global__ void hist_kernel(const int* __restrict__ dst, int* __restrict__ cnt) {
    int e = blockIdx.x * blockDim.x + threadIdx.x;
    if (e < N_EDGES) atomicAdd(&cnt[dst[e]], 1);
}

// single-block exclusive scan of counts -> row_ptr, cursor, ideg
__global__ __launch_bounds__(1024) void scan_kernel(
    const int* __restrict__ cnt, int* __restrict__ row_ptr,
    int* __restrict__ cursor, float* __restrict__ ideg)
{
    __shared__ int part[1024];
    const int t = threadIdx.x;
    const int CH = (N_NODES + 1023) / 1024;   // 98
    int begin = t * CH;
    int end = begin + CH; if (end > N_NODES) end = N_NODES;
    int s = 0;
    for (int i = begin; i < end; i++) s += cnt[i];
    part[t] = s;
    __syncthreads();
    for (int off = 1; off < 1024; off <<= 1) {
        int u = (t >= off) ? part[t - off] : 0;
        __syncthreads();
        part[t] += u;
        __syncthreads();
    }
    int run = part[t] - s;
    for (int i = begin; i < end; i++) {
        int c = cnt[i];
        row_ptr[i] = run;
        cursor[i]  = run;
        ideg[i] = 1.0f / (float)(c > 1 ? c : 1);
        run += c;
    }
    if (t == 1023) row_ptr[N_NODES] = part[1023];
}

// 4 edges per thread: independent atomics -> 4x outstanding per lane
__global__ void fill_kernel(const int* __restrict__ src, const int* __restrict__ dst,
                            int* __restrict__ cursor, int* __restrict__ csr_src) {
    int base = (blockIdx.x * blockDim.x + threadIdx.x) * 4;
    #pragma unroll
    for (int u = 0; u < 4; u++) {
        int e = base + u;
        if (e < N_EDGES) {
            int pos = atomicAdd(&cursor[dst[e]], 1);
            csr_src[pos] = src[e];
        }
    }
}

// ---------------- aggregation, ONE CHANNEL HALF per launch ----------------
// agg[n][half*32 .. half*32+31] = mean_{s in N(n)} h[s][same]
// The half-split keeps the unique h read-set at 12.8MB (one 128B L2 line per
// row) -> L2-resident -> the 205MB of gather reads per pass are L2 hits.
// 16 lanes per node x float2; 8 independent accumulators for MLP.
__global__ __launch_bounds__(256) void agg_half_kernel(
    const float* __restrict__ h,
    const int* __restrict__ row_ptr, const int* __restrict__ csr_src,
    const float* __restrict__ ideg, float* __restrict__ agg, int half)
{
    const int t = threadIdx.x;
    const int node = blockIdx.x * 16 + (t >> 4);
    const int c2 = half * 32 + ((t & 15) << 1);
    if (node >= N_NODES) return;

    const int beg = __ldg(&row_ptr[node]);
    const int end = __ldg(&row_ptr[node + 1]);

    float2 a0 = make_float2(0.f, 0.f);
    float2 a1 = a0, a2 = a0, a3 = a0, a4 = a0, a5 = a0, a6 = a0, a7 = a0;

    int j = beg;
    for (; j + 7 < end; j += 8) {
        int s0 = __ldg(&csr_src[j + 0]);
        int s1 = __ldg(&csr_src[j + 1]);
        int s2 = __ldg(&csr_src[j + 2]);
        int s3 = __ldg(&csr_src[j + 3]);
        int s4 = __ldg(&csr_src[j + 4]);
        int s5 = __ldg(&csr_src[j + 5]);
        int s6 = __ldg(&csr_src[j + 6]);
        int s7 = __ldg(&csr_src[j + 7]);
        float2 v0 = *(const float2*)(h + s0 * C + c2);
        float2 v1 = *(const float2*)(h + s1 * C + c2);
        float2 v2 = *(const float2*)(h + s2 * C + c2);
        float2 v3 = *(const float2*)(h + s3 * C + c2);
        float2 v4 = *(const float2*)(h + s4 * C + c2);
        float2 v5 = *(const float2*)(h + s5 * C + c2);
        float2 v6 = *(const float2*)(h + s6 * C + c2);
        float2 v7 = *(const float2*)(h + s7 * C + c2);
        a0.x += v0.x; a0.y += v0.y;
        a1.x += v1.x; a1.y += v1.y;
        a2.x += v2.x; a2.y += v2.y;
        a3.x += v3.x; a3.y += v3.y;
        a4.x += v4.x; a4.y += v4.y;
        a5.x += v5.x; a5.y += v5.y;
        a6.x += v6.x; a6.y += v6.y;
        a7.x += v7.x; a7.y += v7.y;
    }
    for (; j < end; j++) {
        int s0 = __ldg(&csr_src[j]);
        float2 v0 = *(const float2*)(h + s0 * C + c2);
        a0.x += v0.x; a0.y += v0.y;
    }

    a0.x += a1.x + a2.x + a3.x + a4.x + a5.x + a6.x + a7.x;
    a0.y += a1.y + a2.y + a3.y + a4.y + a5.y + a6.y + a7.y;

    const float id = __ldg(&ideg[node]);
    a0.x *= id; a0.y *= id;
    *(float2*)(agg + node * C + c2) = a0;
}

// ---------------- fused: out = rownorm(h@W1^T + agg@W2^T + b) [-> BN -> ReLU] ----
__global__ __launch_bounds__(256) void sage_fused_kernel(
    const float* __restrict__ h, const float* __restrict__ agg,
    const float* __restrict__ w1, const float* __restrict__ w2,
    const float* __restrict__ b2,
    const float* __restrict__ bn_g, const float* __restrict__ bn_b,
    const float* __restrict__ bn_m, const float* __restrict__ bn_v,
    float* __restrict__ out, int apply_bn)
{
    extern __shared__ float smem[];
    float* sh  = smem;                    // [64][HPAD]
    float* sn  = sh + TILE * HPAD;        // [64][HPAD]
    float* sw1 = sn + TILE * HPAD;        // [64][64] transposed: sw1[k*64+c]
    float* sw2 = sw1 + 64 * 64;           // [64][64]
    float* sb  = sw2 + 64 * 64;           // [64]
    float* ssc = sb + 64;                 // [64] bn scale
    float* sbs = ssc + 64;                // [64] bn bias

    const int t = threadIdx.x;
    const int node0 = blockIdx.x * TILE;

    #pragma unroll
    for (int i = t; i < 64 * 64; i += 256) {
        int c = i >> 6, k = i & 63;
        sw1[k * 64 + c] = w1[i];
        sw2[k * 64 + c] = w2[i];
    }
    if (t < 64) {
        sb[t] = b2[t];
        if (apply_bn) {
            float sc = bn_g[t] * rsqrtf(bn_v[t] + 1e-5f);
            ssc[t] = sc;
            sbs[t] = bn_b[t] - bn_m[t] * sc;
        }
    }

    #pragma unroll
    for (int r = 0; r < 4; r++) {
        int j = t + 256 * r;
        int row = j >> 4;
        int c4 = (j & 15) << 2;
        int node = node0 + row;
        float4 hv = make_float4(0.f, 0.f, 0.f, 0.f);
        float4 av = make_float4(0.f, 0.f, 0.f, 0.f);
        if (node < N_NODES) {
            hv = *(const float4*)(h + node * C + c4);
            av = *(const float4*)(agg + node * C + c4);
        }
        *(float4*)(sh + row * HPAD + c4) = hv;
        *(float4*)(sn + row * HPAD + c4) = av;
    }
    __syncthreads();

    const int cg = (t & 15) << 2;
    const int ng = (t >> 4) << 2;

    float acc[4][4];
    #pragma unroll
    for (int i = 0; i < 4; i++)
        #pragma unroll
        for (int j = 0; j < 4; j++) acc[i][j] = 0.f;

    #pragma unroll 8
    for (int k = 0; k < 64; k++) {
        float4 w1v = *(const float4*)(sw1 + k * 64 + cg);
        float4 w2v = *(const float4*)(sw2 + k * 64 + cg);
        #pragma unroll
        for (int i = 0; i < 4; i++) {
            float a = sh[(ng + i) * HPAD + k];
            float b = sn[(ng + i) * HPAD + k];
            acc[i][0] = fmaf(a, w1v.x, fmaf(b, w2v.x, acc[i][0]));
            acc[i][1] = fmaf(a, w1v.y, fmaf(b, w2v.y, acc[i][1]));
            acc[i][2] = fmaf(a, w1v.z, fmaf(b, w2v.z, acc[i][2]));
            acc[i][3] = fmaf(a, w1v.w, fmaf(b, w2v.w, acc[i][3]));
        }
    }

    float ss[4];
    #pragma unroll
    for (int i = 0; i < 4; i++) {
        float s = 0.f;
        #pragma unroll
        for (int j = 0; j < 4; j++) {
            float v = acc[i][j] + sb[cg + j];
            acc[i][j] = v;
            s = fmaf(v, v, s);
        }
        ss[i] = s;
    }
    #pragma unroll
    for (int m = 1; m < 16; m <<= 1)
        #pragma unroll
        for (int i = 0; i < 4; i++)
            ss[i] += __shfl_xor_sync(0xffffffffu, ss[i], m);

    #pragma unroll
    for (int i = 0; i < 4; i++) {
        int node = node0 + ng + i;
        if (node >= N_NODES) continue;
        float nrm = sqrtf(ss[i]);
        float scale = 1.0f / fmaxf(nrm, 1e-12f);
        float v0 = acc[i][0] * scale;
        float v1 = acc[i][1] * scale;
        float v2 = acc[i][2] * scale;
        float v3 = acc[i][3] * scale;
        if (apply_bn) {
            v0 = fmaxf(fmaf(v0, ssc[cg + 0], sbs[cg + 0]), 0.f);
            v1 = fmaxf(fmaf(v1, ssc[cg + 1], sbs[cg + 1]), 0.f);
            v2 = fmaxf(fmaf(v2, ssc[cg + 2], sbs[cg + 2]), 0.f);
            v3 = fmaxf(fmaf(v3, ssc[cg + 3], sbs[cg + 3]), 0.f);
        }
        float4 o = make_float4(v0, v1, v2, v3);
        *(float4*)(out + node * C + cg) = o;
    }
}

// ---------------- host ----------------
static const int SMEM_BYTES = (2 * TILE * HPAD + 2 * 64 * 64 + 3 * 64) * 4;

extern "C" void kernel_launch(void* const* d_in, const int* in_sizes, int n_in,
                              void* d_out, int out_size) {
    const float* x    = (const float*)d_in[0];
    const int*   esrc = (const int*)d_in[1];
    const int*   edst = (const int*)d_in[2];

    int iw1[3], iw2[3], ib2[3], ibn[2][4];
    if (n_in > 6 && in_sizes[6] == 4096) {
        for (int l = 0; l < 3; l++) { iw1[l] = 3 + 3 * l; iw2[l] = 4 + 3 * l; ib2[l] = 5 + 3 * l; }
        for (int l = 0; l < 2; l++)
            for (int j = 0; j < 4; j++) ibn[l][j] = 12 + 4 * l + j;
    } else {
        iw1[0] = 3;  iw2[0] = 4;  ib2[0] = 5;
        for (int j = 0; j < 4; j++) ibn[0][j] = 6 + j;
        iw1[1] = 10; iw2[1] = 11; ib2[1] = 12;
        for (int j = 0; j < 4; j++) ibn[1][j] = 13 + j;
        iw1[2] = 17; iw2[2] = 18; ib2[2] = 19;
    }

    float *h0, *h1, *agg, *ideg;
    int *cnt, *row_ptr, *cursor, *csr_src;
    cudaGetSymbolAddress((void**)&h0,      g_h0);
    cudaGetSymbolAddress((void**)&h1,      g_h1);
    cudaGetSymbolAddress((void**)&agg,     g_agg);
    cudaGetSymbolAddress((void**)&ideg,    g_ideg);
    cudaGetSymbolAddress((void**)&cnt,     g_cnt);
    cudaGetSymbolAddress((void**)&row_ptr, g_row_ptr);
    cudaGetSymbolAddress((void**)&cursor,  g_cursor);
    cudaGetSymbolAddress((void**)&csr_src, g_csr_src);

    cudaFuncSetAttribute(sage_fused_kernel,
                         cudaFuncAttributeMaxDynamicSharedMemorySize, SMEM_BYTES);

    const int NB_NODE  = (N_NODES + 255) / 256;
    const int NB_EDGE  = (N_EDGES + 255) / 256;
    const int NB_FILL  = (N_EDGES / 4 + 255) / 256;
    const int NB_AGG   = (N_NODES + 15) / 16;
    const int NB_GEMM  = (N_NODES + TILE - 1) / TILE;

    // ---- CSR build (once per launch) ----
    zero_cnt_kernel<<<NB_NODE, 256>>>(cnt);
    hist_kernel<<<NB_EDGE, 256>>>(edst, cnt);
    scan_kernel<<<1, 1024>>>(cnt, row_ptr, cursor, ideg);
    fill_kernel<<<NB_FILL, 256>>>(esrc, edst, cursor, csr_src);

    const float* hin = x;
    float* houts[3] = {h0, h1, (float*)d_out};

    for (int l = 0; l < 3; l++) {
        // serialized channel-half passes: keeps each pass's unique h read-set
        // (12.8MB) L2-resident
        agg_half_kernel<<<NB_AGG, 256>>>(hin, row_ptr, csr_src, ideg, agg, 0);
        agg_half_kernel<<<NB_AGG, 256>>>(hin, row_ptr, csr_src, ideg, agg, 1);
        int has_bn = (l < 2);
        sage_fused_kernel<<<NB_GEMM, 256, SMEM_BYTES>>>(
            hin, agg,
            (const float*)d_in[iw1[l]], (const float*)d_in[iw2[l]],
            (const float*)d_in[ib2[l]],
            has_bn ? (const float*)d_in[ibn[l][0]] : (const float*)d_in[ib2[l]],
            has_bn ? (const float*)d_in[ibn[l][1]] : (const float*)d_in[ib2[l]],
            has_bn ? (const float*)d_in[ibn[l][2]] : (const float*)d_in[ib2[l]],
            has_bn ? (const float*)d_in[ibn[l][3]] : (const float*)d_in[ib2[l]],
            houts[l], has_bn);
        hin = houts[l];
    }
}

// round 6
// speedup vs baseline: 1.0721x; 1.0721x over previous
#include <cuda_runtime.h>
#include <cuda_fp16.h>

#define N_NODES 100000
#define N_EDGES 1600000
#define C 64
#define TILE 64
#define HPAD 68   // padded row stride (floats) for h/hn tiles

// ---------------- scratch (device globals: no allocations allowed) ----------------
__device__ __align__(16) float  g_h0[N_NODES * C];
__device__ __align__(16) float  g_h1[N_NODES * C];
__device__ __align__(16) __half g_h16[N_NODES * C];    // fp16 shadow of current h
__device__ __align__(16) __half g_agg16[N_NODES * C];  // fp16 neighbor mean
__device__ float g_ideg[N_NODES];
__device__ int g_cnt[N_NODES];
__device__ int g_row_ptr[N_NODES + 1];
__device__ int g_cursor[N_NODES];
__device__ int g_csr_src[N_EDGES];

// ---------------- CSR build ----------------
__global__ void zero_cnt_kernel(int* __restrict__ cnt) {
    int i = blockIdx.x * blockDim.x + threadIdx.x;
    if (i < N_NODES) cnt[i] = 0;
}

__global__ void hist_kernel(const int* __restrict__ dst, int* __restrict__ cnt) {
    int e = blockIdx.x * blockDim.x + threadIdx.x;
    if (e < N_EDGES) atomicAdd(&cnt[dst[e]], 1);
}

__global__ __launch_bounds__(1024) void scan_kernel(
    const int* __restrict__ cnt, int* __restrict__ row_ptr,
    int* __restrict__ cursor, float* __restrict__ ideg)
{
    __shared__ int part[1024];
    const int t = threadIdx.x;
    const int CH = (N_NODES + 1023) / 1024;   // 98
    int begin = t * CH;
    int end = begin + CH; if (end > N_NODES) end = N_NODES;
    int s = 0;
    for (int i = begin; i < end; i++) s += cnt[i];
    part[t] = s;
    __syncthreads();
    for (int off = 1; off < 1024; off <<= 1) {
        int u = (t >= off) ? part[t - off] : 0;
        __syncthreads();
        part[t] += u;
        __syncthreads();
    }
    int run = part[t] - s;
    for (int i = begin; i < end; i++) {
        int c = cnt[i];
        row_ptr[i] = run;
        cursor[i]  = run;
        ideg[i] = 1.0f / (float)(c > 1 ? c : 1);
        run += c;
    }
    if (t == 1023) row_ptr[N_NODES] = part[1023];
}

__global__ void fill_kernel(const int* __restrict__ src, const int* __restrict__ dst,
                            int* __restrict__ cursor, int* __restrict__ csr_src) {
    int base = (blockIdx.x * blockDim.x + threadIdx.x) * 4;
    #pragma unroll
    for (int u = 0; u < 4; u++) {
        int e = base + u;
        if (e < N_EDGES) {
            int pos = atomicAdd(&cursor[dst[e]], 1);
            csr_src[pos] = src[e];
        }
    }
}

// ---------------- fp32 -> fp16 convert (layer-0 input only) ----------------
__global__ void f32tof16_kernel(const float* __restrict__ in, __half* __restrict__ out, int n4) {
    int i = blockIdx.x * blockDim.x + threadIdx.x;
    if (i < n4) {
        float4 v = ((const float4*)in)[i];
        __half2 p[2];
        p[0] = __floats2half2_rn(v.x, v.y);
        p[1] = __floats2half2_rn(v.z, v.w);
        ((uint2*)out)[i] = *(uint2*)p;
    }
}

// ---------------- aggregation: agg16[n] = mean_{s in N(n)} h16[s] ----------------
// 8 lanes per node, each lane owns 8 channels (16B). One row = one 128B line.
// 4-way unrolled uint4 loads -> 4x16B in flight per lane; fp32 register accumulation.
__device__ __forceinline__ void accum8(float* a, uint4 r) {
    __half2* p = (__half2*)&r;
    #pragma unroll
    for (int i = 0; i < 4; i++) {
        float2 f = __half22float2(p[i]);
        a[2 * i]     += f.x;
        a[2 * i + 1] += f.y;
    }
}

__global__ __launch_bounds__(256) void agg_f16_kernel(
    const __half* __restrict__ h16,
    const int* __restrict__ row_ptr, const int* __restrict__ csr_src,
    const float* __restrict__ ideg, __half* __restrict__ agg16)
{
    const int t = threadIdx.x;
    const int node = blockIdx.x * 32 + (t >> 3);
    const int c8 = (t & 7) << 3;   // 8 halves per lane
    if (node >= N_NODES) return;

    const int beg = __ldg(&row_ptr[node]);
    const int end = __ldg(&row_ptr[node + 1]);

    float a0[8], a1[8], a2[8], a3[8];
    #pragma unroll
    for (int i = 0; i < 8; i++) { a0[i] = a1[i] = a2[i] = a3[i] = 0.f; }

    int j = beg;
    for (; j + 3 < end; j += 4) {
        int s0 = __ldg(&csr_src[j + 0]);
        int s1 = __ldg(&csr_src[j + 1]);
        int s2 = __ldg(&csr_src[j + 2]);
        int s3 = __ldg(&csr_src[j + 3]);
        uint4 r0 = *(const uint4*)(h16 + s0 * C + c8);
        uint4 r1 = *(const uint4*)(h16 + s1 * C + c8);
        uint4 r2 = *(const uint4*)(h16 + s2 * C + c8);
        uint4 r3 = *(const uint4*)(h16 + s3 * C + c8);
        accum8(a0, r0);
        accum8(a1, r1);
        accum8(a2, r2);
        accum8(a3, r3);
    }
    for (; j < end; j++) {
        int s0 = __ldg(&csr_src[j]);
        uint4 r0 = *(const uint4*)(h16 + s0 * C + c8);
        accum8(a0, r0);
    }

    const float id = __ldg(&ideg[node]);
    __half2 outp[4];
    #pragma unroll
    for (int i = 0; i < 4; i++) {
        float x0 = (a0[2 * i]     + a1[2 * i]     + a2[2 * i]     + a3[2 * i])     * id;
        float x1 = (a0[2 * i + 1] + a1[2 * i + 1] + a2[2 * i + 1] + a3[2 * i + 1]) * id;
        outp[i] = __floats2half2_rn(x0, x1);
    }
    *(uint4*)(agg16 + node * C + c8) = *(uint4*)outp;
}

// ---------------- fused: out = rownorm(h@W1^T + agg@W2^T + b) [-> BN -> ReLU] ----
// Also emits fp16 shadow of the output (next layer's gather input) when write_h16.
__global__ __launch_bounds__(256) void sage_fused_kernel(
    const float* __restrict__ h, const __half* __restrict__ agg16,
    const float* __restrict__ w1, const float* __restrict__ w2,
    const float* __restrict__ b2,
    const float* __restrict__ bn_g, const float* __restrict__ bn_b,
    const float* __restrict__ bn_m, const float* __restrict__ bn_v,
    float* __restrict__ out, __half* __restrict__ out16,
    int apply_bn, int write_h16)
{
    extern __shared__ float smem[];
    float* sh  = smem;                    // [64][HPAD]
    float* sn  = sh + TILE * HPAD;        // [64][HPAD]
    float* sw1 = sn + TILE * HPAD;        // [64][64] transposed: sw1[k*64+c]
    float* sw2 = sw1 + 64 * 64;           // [64][64]
    float* sb  = sw2 + 64 * 64;           // [64]
    float* ssc = sb + 64;                 // [64] bn scale
    float* sbs = ssc + 64;                // [64] bn bias

    const int t = threadIdx.x;
    const int node0 = blockIdx.x * TILE;

    #pragma unroll
    for (int i = t; i < 64 * 64; i += 256) {
        int c = i >> 6, k = i & 63;
        sw1[k * 64 + c] = w1[i];
        sw2[k * 64 + c] = w2[i];
    }
    if (t < 64) {
        sb[t] = b2[t];
        if (apply_bn) {
            float sc = bn_g[t] * rsqrtf(bn_v[t] + 1e-5f);
            ssc[t] = sc;
            sbs[t] = bn_b[t] - bn_m[t] * sc;
        }
    }

    #pragma unroll
    for (int r = 0; r < 4; r++) {
        int j = t + 256 * r;
        int row = j >> 4;
        int c4 = (j & 15) << 2;
        int node = node0 + row;
        float4 hv = make_float4(0.f, 0.f, 0.f, 0.f);
        float4 av = make_float4(0.f, 0.f, 0.f, 0.f);
        if (node < N_NODES) {
            hv = *(const float4*)(h + node * C + c4);
            uint2 raw = *(const uint2*)(agg16 + node * C + c4);
            __half2* hp = (__half2*)&raw;
            float2 f01 = __half22float2(hp[0]);
            float2 f23 = __half22float2(hp[1]);
            av = make_float4(f01.x, f01.y, f23.x, f23.y);
        }
        *(float4*)(sh + row * HPAD + c4) = hv;
        *(float4*)(sn + row * HPAD + c4) = av;
    }
    __syncthreads();

    const int cg = (t & 15) << 2;
    const int ng = (t >> 4) << 2;

    float acc[4][4];
    #pragma unroll
    for (int i = 0; i < 4; i++)
        #pragma unroll
        for (int j = 0; j < 4; j++) acc[i][j] = 0.f;

    #pragma unroll 8
    for (int k = 0; k < 64; k++) {
        float4 w1v = *(const float4*)(sw1 + k * 64 + cg);
        float4 w2v = *(const float4*)(sw2 + k * 64 + cg);
        #pragma unroll
        for (int i = 0; i < 4; i++) {
            float a = sh[(ng + i) * HPAD + k];
            float b = sn[(ng + i) * HPAD + k];
            acc[i][0] = fmaf(a, w1v.x, fmaf(b, w2v.x, acc[i][0]));
            acc[i][1] = fmaf(a, w1v.y, fmaf(b, w2v.y, acc[i][1]));
            acc[i][2] = fmaf(a, w1v.z, fmaf(b, w2v.z, acc[i][2]));
            acc[i][3] = fmaf(a, w1v.w, fmaf(b, w2v.w, acc[i][3]));
        }
    }

    float ss[4];
    #pragma unroll
    for (int i = 0; i < 4; i++) {
        float s = 0.f;
        #pragma unroll
        for (int j = 0; j < 4; j++) {
            float v = acc[i][j] + sb[cg + j];
            acc[i][j] = v;
            s = fmaf(v, v, s);
        }
        ss[i] = s;
    }
    #pragma unroll
    for (int m = 1; m < 16; m <<= 1)
        #pragma unroll
        for (int i = 0; i < 4; i++)
            ss[i] += __shfl_xor_sync(0xffffffffu, ss[i], m);

    #pragma unroll
    for (int i = 0; i < 4; i++) {
        int node = node0 + ng + i;
        if (node >= N_NODES) continue;
        float nrm = sqrtf(ss[i]);
        float scale = 1.0f / fmaxf(nrm, 1e-12f);
        float v0 = acc[i][0] * scale;
        float v1 = acc[i][1] * scale;
        float v2 = acc[i][2] * scale;
        float v3 = acc[i][3] * scale;
        if (apply_bn) {
            v0 = fmaxf(fmaf(v0, ssc[cg + 0], sbs[cg + 0]), 0.f);
            v1 = fmaxf(fmaf(v1, ssc[cg + 1], sbs[cg + 1]), 0.f);
            v2 = fmaxf(fmaf(v2, ssc[cg + 2], sbs[cg + 2]), 0.f);
            v3 = fmaxf(fmaf(v3, ssc[cg + 3], sbs[cg + 3]), 0.f);
        }
        float4 o = make_float4(v0, v1, v2, v3);
        *(float4*)(out + node * C + cg) = o;
        if (write_h16) {
            __half2 q[2];
            q[0] = __floats2half2_rn(v0, v1);
            q[1] = __floats2half2_rn(v2, v3);
            *(uint2*)(out16 + node * C + cg) = *(uint2*)q;
        }
    }
}

// ---------------- host ----------------
static const int SMEM_BYTES = (2 * TILE * HPAD + 2 * 64 * 64 + 3 * 64) * 4;

extern "C" void kernel_launch(void* const* d_in, const int* in_sizes, int n_in,
                              void* d_out, int out_size) {
    const float* x    = (const float*)d_in[0];
    const int*   esrc = (const int*)d_in[1];
    const int*   edst = (const int*)d_in[2];

    int iw1[3], iw2[3], ib2[3], ibn[2][4];
    if (n_in > 6 && in_sizes[6] == 4096) {
        for (int l = 0; l < 3; l++) { iw1[l] = 3 + 3 * l; iw2[l] = 4 + 3 * l; ib2[l] = 5 + 3 * l; }
        for (int l = 0; l < 2; l++)
            for (int j = 0; j < 4; j++) ibn[l][j] = 12 + 4 * l + j;
    } else {
        iw1[0] = 3;  iw2[0] = 4;  ib2[0] = 5;
        for (int j = 0; j < 4; j++) ibn[0][j] = 6 + j;
        iw1[1] = 10; iw2[1] = 11; ib2[1] = 12;
        for (int j = 0; j < 4; j++) ibn[1][j] = 13 + j;
        iw1[2] = 17; iw2[2] = 18; ib2[2] = 19;
    }

    float *h0, *h1, *ideg;
    __half *h16, *agg16;
    int *cnt, *row_ptr, *cursor, *csr_src;
    cudaGetSymbolAddress((void**)&h0,      g_h0);
    cudaGetSymbolAddress((void**)&h1,      g_h1);
    cudaGetSymbolAddress((void**)&h16,     g_h16);
    cudaGetSymbolAddress((void**)&agg16,   g_agg16);
    cudaGetSymbolAddress((void**)&ideg,    g_ideg);
    cudaGetSymbolAddress((void**)&cnt,     g_cnt);
    cudaGetSymbolAddress((void**)&row_ptr, g_row_ptr);
    cudaGetSymbolAddress((void**)&cursor,  g_cursor);
    cudaGetSymbolAddress((void**)&csr_src, g_csr_src);

    cudaFuncSetAttribute(sage_fused_kernel,
                         cudaFuncAttributeMaxDynamicSharedMemorySize, SMEM_BYTES);

    const int NB_NODE = (N_NODES + 255) / 256;
    const int NB_EDGE = (N_EDGES + 255) / 256;
    const int NB_FILL = (N_EDGES / 4 + 255) / 256;
    const int NB_CVT  = (N_NODES * C / 4 + 255) / 256;
    const int NB_AGG  = (N_NODES + 31) / 32;
    const int NB_GEMM = (N_NODES + TILE - 1) / TILE;

    // ---- CSR build (once per launch) ----
    zero_cnt_kernel<<<NB_NODE, 256>>>(cnt);
    hist_kernel<<<NB_EDGE, 256>>>(edst, cnt);
    scan_kernel<<<1, 1024>>>(cnt, row_ptr, cursor, ideg);
    fill_kernel<<<NB_FILL, 256>>>(esrc, edst, cursor, csr_src);

    // layer-0 gather input: fp16 shadow of x
    f32tof16_kernel<<<NB_CVT, 256>>>(x, h16, N_NODES * C / 4);

    const float* hin = x;
    float* houts[3] = {h0, h1, (float*)d_out};

    for (int l = 0; l < 3; l++) {
        agg_f16_kernel<<<NB_AGG, 256>>>(h16, row_ptr, csr_src, ideg, agg16);
        int has_bn = (l < 2);
        // fused kernel overwrites h16 with this layer's output (safe: agg done)
        sage_fused_kernel<<<NB_GEMM, 256, SMEM_BYTES>>>(
            hin, agg16,
            (const float*)d_in[iw1[l]], (const float*)d_in[iw2[l]],
            (const float*)d_in[ib2[l]],
            has_bn ? (const float*)d_in[ibn[l][0]] : (const float*)d_in[ib2[l]],
            has_bn ? (const float*)d_in[ibn[l][1]] : (const float*)d_in[ib2[l]],
            has_bn ? (const float*)d_in[ibn[l][2]] : (const float*)d_in[ib2[l]],
            has_bn ? (const float*)d_in[ibn[l][3]] : (const float*)d_in[ib2[l]],
            houts[l], h16, has_bn, (l < 2) ? 1 : 0);
        hin = houts[l];
    }
}

// round 9
// speedup vs baseline: 1.5905x; 1.4836x over previous
#include <cuda_runtime.h>
#include <cuda_fp16.h>
#include <mma.h>

#define N_NODES 100000
#define N_EDGES 1600000
#define C 64
#define LDA 136   // halves; 272B row stride
#define LDB 72    // halves; 144B row stride
#define LDO 68    // floats; 272B row stride (aliases A region)

// ---------------- scratch (device globals: no allocations allowed) ----------------
__device__ __align__(16) __half g_h16[N_NODES * C];    // fp16 current features
__device__ __align__(16) __half g_agg16[N_NODES * C];  // fp16 neighbor mean
__device__ __align__(16) __half g_wc[3][128 * 64];     // per-layer combined [W1;W2]^T fp16
__device__ float g_ideg[N_NODES];
__device__ int g_cnt[N_NODES];
__device__ int g_row_ptr[N_NODES + 1];
__device__ int g_cursor[N_NODES];
__device__ int g_csr_src[N_EDGES];

// ---------------- CSR build ----------------
__global__ void zero_cnt_kernel(int* __restrict__ cnt) {
    int i = blockIdx.x * blockDim.x + threadIdx.x;
    if (i < N_NODES) cnt[i] = 0;
}

__global__ void hist_kernel(const int* __restrict__ dst, int* __restrict__ cnt) {
    int e = blockIdx.x * blockDim.x + threadIdx.x;
    if (e < N_EDGES) atomicAdd(&cnt[dst[e]], 1);
}

__global__ __launch_bounds__(1024) void scan_kernel(
    const int* __restrict__ cnt, int* __restrict__ row_ptr,
    int* __restrict__ cursor, float* __restrict__ ideg)
{
    __shared__ int part[1024];
    const int t = threadIdx.x;
    const int CH = (N_NODES + 1023) / 1024;   // 98
    int begin = t * CH;
    int end = begin + CH; if (end > N_NODES) end = N_NODES;
    int s = 0;
    for (int i = begin; i < end; i++) s += cnt[i];
    part[t] = s;
    __syncthreads();
    for (int off = 1; off < 1024; off <<= 1) {
        int u = (t >= off) ? part[t - off] : 0;
        __syncthreads();
        part[t] += u;
        __syncthreads();
    }
    int run = part[t] - s;
    for (int i = begin; i < end; i++) {
        int c = cnt[i];
        row_ptr[i] = run;
        cursor[i]  = run;
        ideg[i] = 1.0f / (float)(c > 1 ? c : 1);
        run += c;
    }
    if (t == 1023) row_ptr[N_NODES] = part[1023];
}

__global__ void fill_kernel(const int* __restrict__ src, const int* __restrict__ dst,
                            int* __restrict__ cursor, int* __restrict__ csr_src) {
    int base = (blockIdx.x * blockDim.x + threadIdx.x) * 4;
    #pragma unroll
    for (int u = 0; u < 4; u++) {
        int e = base + u;
        if (e < N_EDGES) {
            int pos = atomicAdd(&cursor[dst[e]], 1);
            csr_src[pos] = src[e];
        }
    }
}

// ---------------- fp32 -> fp16 convert (layer-0 input) ----------------
__global__ void f32tof16_kernel(const float* __restrict__ in, __half* __restrict__ out, int n4) {
    int i = blockIdx.x * blockDim.x + threadIdx.x;
    if (i < n4) {
        float4 v = ((const float4*)in)[i];
        __half2 p[2];
        p[0] = __floats2half2_rn(v.x, v.y);
        p[1] = __floats2half2_rn(v.z, v.w);
        ((uint2*)out)[i] = *(uint2*)p;
    }
}

// ---------------- weight prep: wc[k][n] = (k<64 ? w1[n][k] : w2[n][k-64]) fp16 ----
__global__ void wconv_kernel(const float* __restrict__ w1, const float* __restrict__ w2,
                             __half* __restrict__ wc) {
    int i = blockIdx.x * blockDim.x + threadIdx.x;   // 0..8191
    if (i < 8192) {
        int k = i >> 6, n = i & 63;
        float v = (k < 64) ? w1[n * 64 + k] : w2[n * 64 + (k - 64)];
        wc[k * 64 + n] = __float2half(v);
    }
}

// ---------------- aggregation: agg16[n] = mean_{s in N(n)} h16[s] ----------------
__device__ __forceinline__ void accum8(float* a, uint4 r) {
    __half2* p = (__half2*)&r;
    #pragma unroll
    for (int i = 0; i < 4; i++) {
        float2 f = __half22float2(p[i]);
        a[2 * i]     += f.x;
        a[2 * i + 1] += f.y;
    }
}

__global__ __launch_bounds__(256) void agg_f16_kernel(
    const __half* __restrict__ h16,
    const int* __restrict__ row_ptr, const int* __restrict__ csr_src,
    const float* __restrict__ ideg, __half* __restrict__ agg16)
{
    const int t = threadIdx.x;
    const int node = blockIdx.x * 32 + (t >> 3);
    const int c8 = (t & 7) << 3;
    if (node >= N_NODES) return;

    const int beg = __ldg(&row_ptr[node]);
    const int end = __ldg(&row_ptr[node + 1]);

    float a0[8], a1[8], a2[8], a3[8];
    #pragma unroll
    for (int i = 0; i < 8; i++) { a0[i] = a1[i] = a2[i] = a3[i] = 0.f; }

    int j = beg;
    for (; j + 3 < end; j += 4) {
        int s0 = __ldg(&csr_src[j + 0]);
        int s1 = __ldg(&csr_src[j + 1]);
        int s2 = __ldg(&csr_src[j + 2]);
        int s3 = __ldg(&csr_src[j + 3]);
        uint4 r0 = *(const uint4*)(h16 + s0 * C + c8);
        uint4 r1 = *(const uint4*)(h16 + s1 * C + c8);
        uint4 r2 = *(const uint4*)(h16 + s2 * C + c8);
        uint4 r3 = *(const uint4*)(h16 + s3 * C + c8);
        accum8(a0, r0);
        accum8(a1, r1);
        accum8(a2, r2);
        accum8(a3, r3);
    }
    for (; j < end; j++) {
        int s0 = __ldg(&csr_src[j]);
        uint4 r0 = *(const uint4*)(h16 + s0 * C + c8);
        accum8(a0, r0);
    }

    const float id = __ldg(&ideg[node]);
    __half2 outp[4];
    #pragma unroll
    for (int i = 0; i < 4; i++) {
        float x0 = (a0[2 * i]     + a1[2 * i]     + a2[2 * i]     + a3[2 * i])     * id;
        float x1 = (a0[2 * i + 1] + a1[2 * i + 1] + a2[2 * i + 1] + a3[2 * i + 1]) * id;
        outp[i] = __floats2half2_rn(x0, x1);
    }
    *(uint4*)(agg16 + node * C + c8) = *(uint4*)outp;
}

// ---------------- tensor-core fused layer (WMMA, no inline asm) ----------------
// out[m, 0:64] = rownorm( [h16 | agg16][m, 0:128] @ wc + b ) [-> BN -> ReLU]
// Block = 128 threads (4 warps), 64 rows/block. Warp w -> rows 16w..16w+15,
// 4 wmma 16x16x16 acc fragments over 8 k-steps. Accumulators staged through
// smem (aliasing the A region, warp-local rows) for a coalesced epilogue.
__global__ __launch_bounds__(128) void sage_wmma_kernel(
    const __half* __restrict__ h16, const __half* __restrict__ agg16,
    const __half* __restrict__ wc,
    const float* __restrict__ b2,
    const float* __restrict__ bn_g, const float* __restrict__ bn_b,
    const float* __restrict__ bn_m, const float* __restrict__ bn_v,
    float* __restrict__ out32, __half* __restrict__ out16,
    int apply_bn, int write32)
{
    __shared__ __align__(16) __half sa[64 * LDA];   // 17408 B; later aliased as so[64][LDO] floats
    __shared__ __align__(16) __half sb[128 * LDB];  // 18432 B
    __shared__ float sbias[64], ssc[64], sbs[64], snorm[64];

    const int t = threadIdx.x;
    const int lane = t & 31, warp = t >> 5;
    const int node0 = blockIdx.x * 64;
    float* so = reinterpret_cast<float*>(sa);

    // B: wc[128][64] -> sb[k][n] (padded rows)
    for (int i = t; i < 1024; i += 128) {           // 1024 chunks x 8 halves
        int k = i >> 3, c8 = (i & 7) << 3;
        *(uint4*)&sb[k * LDB + c8] = *(const uint4*)&wc[k * 64 + c8];
    }
    if (t < 64) {
        sbias[t] = b2[t];
        if (apply_bn) {
            float sc = bn_g[t] * rsqrtf(bn_v[t] + 1e-5f);
            ssc[t] = sc;
            sbs[t] = bn_b[t] - bn_m[t] * sc;
        }
    }
    // A: [64 rows][k=0:64 h16 | k=64:128 agg16]
    for (int i = t; i < 1024; i += 128) {           // 64 rows x 16 chunks
        int row = i >> 4, c8 = (i & 15) << 3;
        int node = node0 + row;
        uint4 v = make_uint4(0, 0, 0, 0);
        if (node < N_NODES)
            v = (c8 < 64) ? *(const uint4*)&h16[node * C + c8]
                          : *(const uint4*)&agg16[node * C + c8 - 64];
        *(uint4*)&sa[row * LDA + c8] = v;
    }
    __syncthreads();

    using namespace nvcuda;
    wmma::fragment<wmma::accumulator, 16, 16, 16, float> acc[4];
    #pragma unroll
    for (int n = 0; n < 4; n++) wmma::fill_fragment(acc[n], 0.0f);

    const int m0 = warp * 16;
    #pragma unroll
    for (int kc = 0; kc < 8; kc++) {
        const int k0 = kc * 16;
        wmma::fragment<wmma::matrix_a, 16, 16, 16, __half, wmma::row_major> af;
        wmma::load_matrix_sync(af, sa + m0 * LDA + k0, LDA);
        #pragma unroll
        for (int n = 0; n < 4; n++) {
            wmma::fragment<wmma::matrix_b, 16, 16, 16, __half, wmma::row_major> bf;
            wmma::load_matrix_sync(bf, sb + k0 * LDB + n * 16, LDB);
            wmma::mma_sync(acc[n], af, bf, acc[n]);
        }
    }

    // Stage accumulators to smem over the (now consumed, warp-local) A rows.
    #pragma unroll
    for (int n = 0; n < 4; n++)
        wmma::store_matrix_sync(so + m0 * LDO + n * 16, acc[n], LDO, wmma::mem_row_major);

    // phase 1: row norms (thread pair per row; warp-local rows, no sync needed yet)
    {
        int row = t >> 1, halfsel = t & 1;
        float s = 0.f;
        #pragma unroll
        for (int c = 0; c < 32; c++) {
            int col = halfsel * 32 + c;
            float v = so[row * LDO + col] + sbias[col];
            s = fmaf(v, v, s);
        }
        s += __shfl_xor_sync(0xffffffffu, s, 1);
        if (halfsel == 0) snorm[row] = 1.0f / fmaxf(sqrtf(s), 1e-12f);
    }
    __syncthreads();

    // phase 2: coalesced float4-granule epilogue + store
    #pragma unroll
    for (int it = 0; it < 8; it++) {
        int i = t + 128 * it;            // 0..1023 float4 units over 64x64
        int row = i >> 4;
        int c4 = (i & 15) << 2;
        int node = node0 + row;
        if (node >= N_NODES) continue;
        float sc = snorm[row];
        float v0 = (so[row * LDO + c4 + 0] + sbias[c4 + 0]) * sc;
        float v1 = (so[row * LDO + c4 + 1] + sbias[c4 + 1]) * sc;
        float v2 = (so[row * LDO + c4 + 2] + sbias[c4 + 2]) * sc;
        float v3 = (so[row * LDO + c4 + 3] + sbias[c4 + 3]) * sc;
        if (apply_bn) {
            v0 = fmaxf(fmaf(v0, ssc[c4 + 0], sbs[c4 + 0]), 0.f);
            v1 = fmaxf(fmaf(v1, ssc[c4 + 1], sbs[c4 + 1]), 0.f);
            v2 = fmaxf(fmaf(v2, ssc[c4 + 2], sbs[c4 + 2]), 0.f);
            v3 = fmaxf(fmaf(v3, ssc[c4 + 3], sbs[c4 + 3]), 0.f);
        }
        if (write32) {
            *(float4*)&out32[node * C + c4] = make_float4(v0, v1, v2, v3);
        } else {
            __half2 q[2];
            q[0] = __floats2half2_rn(v0, v1);
            q[1] = __floats2half2_rn(v2, v3);
            *(uint2*)&out16[node * C + c4] = *(uint2*)q;
        }
    }
}

// ---------------- host ----------------
extern "C" void kernel_launch(void* const* d_in, const int* in_sizes, int n_in,
                              void* d_out, int out_size) {
    const float* x    = (const float*)d_in[0];
    const int*   esrc = (const int*)d_in[1];
    const int*   edst = (const int*)d_in[2];

    int iw1[3], iw2[3], ib2[3], ibn[2][4];
    if (n_in > 6 && in_sizes[6] == 4096) {
        for (int l = 0; l < 3; l++) { iw1[l] = 3 + 3 * l; iw2[l] = 4 + 3 * l; ib2[l] = 5 + 3 * l; }
        for (int l = 0; l < 2; l++)
            for (int j = 0; j < 4; j++) ibn[l][j] = 12 + 4 * l + j;
    } else {
        iw1[0] = 3;  iw2[0] = 4;  ib2[0] = 5;
        for (int j = 0; j < 4; j++) ibn[0][j] = 6 + j;
        iw1[1] = 10; iw2[1] = 11; ib2[1] = 12;
        for (int j = 0; j < 4; j++) ibn[1][j] = 13 + j;
        iw1[2] = 17; iw2[2] = 18; ib2[2] = 19;
    }

    __half *h16, *agg16, *wc;
    float *ideg;
    int *cnt, *row_ptr, *cursor, *csr_src;
    cudaGetSymbolAddress((void**)&h16,     g_h16);
    cudaGetSymbolAddress((void**)&agg16,   g_agg16);
    cudaGetSymbolAddress((void**)&wc,      g_wc);
    cudaGetSymbolAddress((void**)&ideg,    g_ideg);
    cudaGetSymbolAddress((void**)&cnt,     g_cnt);
    cudaGetSymbolAddress((void**)&row_ptr, g_row_ptr);
    cudaGetSymbolAddress((void**)&cursor,  g_cursor);
    cudaGetSymbolAddress((void**)&csr_src, g_csr_src);

    const int NB_NODE = (N_NODES + 255) / 256;
    const int NB_EDGE = (N_EDGES + 255) / 256;
    const int NB_FILL = (N_EDGES / 4 + 255) / 256;
    const int NB_CVT  = (N_NODES * C / 4 + 255) / 256;
    const int NB_AGG  = (N_NODES + 31) / 32;
    const int NB_MMA  = (N_NODES + 63) / 64;

    // ---- CSR build (once; graph static across layers) ----
    zero_cnt_kernel<<<NB_NODE, 256>>>(cnt);
    hist_kernel<<<NB_EDGE, 256>>>(edst, cnt);
    scan_kernel<<<1, 1024>>>(cnt, row_ptr, cursor, ideg);
    fill_kernel<<<NB_FILL, 256>>>(esrc, edst, cursor, csr_src);

    // fp16 shadow of x + per-layer combined fp16 weights
    f32tof16_kernel<<<NB_CVT, 256>>>(x, h16, N_NODES * C / 4);
    for (int l = 0; l < 3; l++)
        wconv_kernel<<<32, 256>>>((const float*)d_in[iw1[l]],
                                  (const float*)d_in[iw2[l]],
                                  wc + l * 128 * 64);

    for (int l = 0; l < 3; l++) {
        agg_f16_kernel<<<NB_AGG, 256>>>(h16, row_ptr, csr_src, ideg, agg16);
        int has_bn = (l < 2);
        // in-place h16 update is safe: each block reads only its own 64 rows
        // into smem before writing them back.
        sage_wmma_kernel<<<NB_MMA, 128>>>(
            h16, agg16, wc + l * 128 * 64,
            (const float*)d_in[ib2[l]],
            has_bn ? (const float*)d_in[ibn[l][0]] : (const float*)d_in[ib2[l]],
            has_bn ? (const float*)d_in[ibn[l][1]] : (const float*)d_in[ib2[l]],
            has_bn ? (const float*)d_in[ibn[l][2]] : (const float*)d_in[ib2[l]],
            has_bn ? (const float*)d_in[ibn[l][3]] : (const float*)d_in[ib2[l]],
            (float*)d_out, h16, has_bn, (l == 2) ? 1 : 0);
    }
}

// round 10
// speedup vs baseline: 1.5983x; 1.0049x over previous
#include <cuda_runtime.h>
#include <cuda_fp16.h>
#include <mma.h>

#define N_NODES 100000
#define N_EDGES 1600000
#define C 64
#define LDA 136   // halves; 272B row stride
#define LDB 72    // halves; 144B row stride
#define LDO 68    // floats; 272B row stride (aliases A region)

// ---------------- scratch (device globals: no allocations allowed) ----------------
__device__ __align__(16) __half g_h16[N_NODES * C];    // fp16 current features
__device__ __align__(16) __half g_agg16[N_NODES * C];  // fp16 neighbor mean
__device__ __align__(16) __half g_wc[3][128 * 64];     // per-layer combined [W1;W2]^T fp16
__device__ float g_ideg[N_NODES];
__device__ int g_cnt[N_NODES];
__device__ int g_row_ptr[N_NODES + 1];
__device__ int g_cursor[N_NODES];
__device__ int g_csr_src[N_EDGES];

// ---------------- CSR build ----------------
__global__ void zero_cnt_kernel(int* __restrict__ cnt) {
    int i = blockIdx.x * blockDim.x + threadIdx.x;
    if (i < N_NODES) cnt[i] = 0;
}

__global__ void hist_kernel(const int* __restrict__ dst, int* __restrict__ cnt) {
    int e = blockIdx.x * blockDim.x + threadIdx.x;
    if (e < N_EDGES) atomicAdd(&cnt[dst[e]], 1);
}

__global__ __launch_bounds__(1024) void scan_kernel(
    const int* __restrict__ cnt, int* __restrict__ row_ptr,
    int* __restrict__ cursor, float* __restrict__ ideg)
{
    __shared__ int part[1024];
    const int t = threadIdx.x;
    const int CH = (N_NODES + 1023) / 1024;   // 98
    int begin = t * CH;
    int end = begin + CH; if (end > N_NODES) end = N_NODES;
    int s = 0;
    for (int i = begin; i < end; i++) s += cnt[i];
    part[t] = s;
    __syncthreads();
    for (int off = 1; off < 1024; off <<= 1) {
        int u = (t >= off) ? part[t - off] : 0;
        __syncthreads();
        part[t] += u;
        __syncthreads();
    }
    int run = part[t] - s;
    for (int i = begin; i < end; i++) {
        int c = cnt[i];
        row_ptr[i] = run;
        cursor[i]  = run;
        ideg[i] = 1.0f / (float)(c > 1 ? c : 1);
        run += c;
    }
    if (t == 1023) row_ptr[N_NODES] = part[1023];
}

// 8 edges per thread: independent atomics -> 8 outstanding per lane
__global__ void fill_kernel(const int* __restrict__ src, const int* __restrict__ dst,
                            int* __restrict__ cursor, int* __restrict__ csr_src) {
    int base = (blockIdx.x * blockDim.x + threadIdx.x) * 8;
    #pragma unroll
    for (int u = 0; u < 8; u++) {
        int e = base + u;
        if (e < N_EDGES) {
            int pos = atomicAdd(&cursor[dst[e]], 1);
            csr_src[pos] = src[e];
        }
    }
}

// ---------------- prep: x -> fp16 shadow AND all 3 layers' combined weights ----
// (fused so that launch #6 is agg_f16_kernel -> ncu -s 5 -c 1 profiles it)
#define NB_CVT_K ((N_NODES * C / 4 + 255) / 256)
__global__ void prep_kernel(const float* __restrict__ x, __half* __restrict__ h16,
                            const float* __restrict__ w1_0, const float* __restrict__ w2_0,
                            const float* __restrict__ w1_1, const float* __restrict__ w2_1,
                            const float* __restrict__ w1_2, const float* __restrict__ w2_2,
                            __half* __restrict__ wc) {
    int b = blockIdx.x;
    if (b < NB_CVT_K) {
        int i = b * 256 + threadIdx.x;
        if (i < N_NODES * C / 4) {
            float4 v = ((const float4*)x)[i];
            __half2 p[2];
            p[0] = __floats2half2_rn(v.x, v.y);
            p[1] = __floats2half2_rn(v.z, v.w);
            ((uint2*)h16)[i] = *(uint2*)p;
        }
    } else {
        int i = (b - NB_CVT_K) * 256 + threadIdx.x;   // 0..24575 = 3 layers x 8192
        if (i < 3 * 8192) {
            int l = i >> 13;
            int r = i & 8191;
            int k = r >> 6, n = r & 63;
            const float* w1 = (l == 0) ? w1_0 : (l == 1) ? w1_1 : w1_2;
            const float* w2 = (l == 0) ? w2_0 : (l == 1) ? w2_1 : w2_2;
            float v = (k < 64) ? w1[n * 64 + k] : w2[n * 64 + (k - 64)];
            wc[l * 8192 + k * 64 + n] = __float2half(v);
        }
    }
}

// ---------------- aggregation: agg16[n] = mean_{s in N(n)} h16[s] ----------------
__device__ __forceinline__ void accum8(float* a, uint4 r) {
    __half2* p = (__half2*)&r;
    #pragma unroll
    for (int i = 0; i < 4; i++) {
        float2 f = __half22float2(p[i]);
        a[2 * i]     += f.x;
        a[2 * i + 1] += f.y;
    }
}

__global__ __launch_bounds__(256) void agg_f16_kernel(
    const __half* __restrict__ h16,
    const int* __restrict__ row_ptr, const int* __restrict__ csr_src,
    const float* __restrict__ ideg, __half* __restrict__ agg16)
{
    const int t = threadIdx.x;
    const int node = blockIdx.x * 32 + (t >> 3);
    const int c8 = (t & 7) << 3;
    if (node >= N_NODES) return;

    const int beg = __ldg(&row_ptr[node]);
    const int end = __ldg(&row_ptr[node + 1]);

    float a0[8], a1[8], a2[8], a3[8];
    #pragma unroll
    for (int i = 0; i < 8; i++) { a0[i] = a1[i] = a2[i] = a3[i] = 0.f; }

    int j = beg;
    for (; j + 3 < end; j += 4) {
        int s0 = __ldg(&csr_src[j + 0]);
        int s1 = __ldg(&csr_src[j + 1]);
        int s2 = __ldg(&csr_src[j + 2]);
        int s3 = __ldg(&csr_src[j + 3]);
        uint4 r0 = *(const uint4*)(h16 + s0 * C + c8);
        uint4 r1 = *(const uint4*)(h16 + s1 * C + c8);
        uint4 r2 = *(const uint4*)(h16 + s2 * C + c8);
        uint4 r3 = *(const uint4*)(h16 + s3 * C + c8);
        accum8(a0, r0);
        accum8(a1, r1);
        accum8(a2, r2);
        accum8(a3, r3);
    }
    for (; j < end; j++) {
        int s0 = __ldg(&csr_src[j]);
        uint4 r0 = *(const uint4*)(h16 + s0 * C + c8);
        accum8(a0, r0);
    }

    const float id = __ldg(&ideg[node]);
    __half2 outp[4];
    #pragma unroll
    for (int i = 0; i < 4; i++) {
        float x0 = (a0[2 * i]     + a1[2 * i]     + a2[2 * i]     + a3[2 * i])     * id;
        float x1 = (a0[2 * i + 1] + a1[2 * i + 1] + a2[2 * i + 1] + a3[2 * i + 1]) * id;
        outp[i] = __floats2half2_rn(x0, x1);
    }
    *(uint4*)(agg16 + node * C + c8) = *(uint4*)outp;
}

// ---------------- tensor-core fused layer (WMMA) ----------------
__global__ __launch_bounds__(128) void sage_wmma_kernel(
    const __half* __restrict__ h16, const __half* __restrict__ agg16,
    const __half* __restrict__ wc,
    const float* __restrict__ b2,
    const float* __restrict__ bn_g, const float* __restrict__ bn_b,
    const float* __restrict__ bn_m, const float* __restrict__ bn_v,
    float* __restrict__ out32, __half* __restrict__ out16,
    int apply_bn, int write32)
{
    __shared__ __align__(16) __half sa[64 * LDA];   // later aliased as so[64][LDO] floats
    __shared__ __align__(16) __half sb[128 * LDB];
    __shared__ float sbias[64], ssc[64], sbs[64], snorm[64];

    const int t = threadIdx.x;
    const int warp = t >> 5;
    const int node0 = blockIdx.x * 64;
    float* so = reinterpret_cast<float*>(sa);

    for (int i = t; i < 1024; i += 128) {           // B: wc[128][64] -> sb
        int k = i >> 3, c8 = (i & 7) << 3;
        *(uint4*)&sb[k * LDB + c8] = *(const uint4*)&wc[k * 64 + c8];
    }
    if (t < 64) {
        sbias[t] = b2[t];
        if (apply_bn) {
            float sc = bn_g[t] * rsqrtf(bn_v[t] + 1e-5f);
            ssc[t] = sc;
            sbs[t] = bn_b[t] - bn_m[t] * sc;
        }
    }
    for (int i = t; i < 1024; i += 128) {           // A: [h16 | agg16]
        int row = i >> 4, c8 = (i & 15) << 3;
        int node = node0 + row;
        uint4 v = make_uint4(0, 0, 0, 0);
        if (node < N_NODES)
            v = (c8 < 64) ? *(const uint4*)&h16[node * C + c8]
                          : *(const uint4*)&agg16[node * C + c8 - 64];
        *(uint4*)&sa[row * LDA + c8] = v;
    }
    __syncthreads();

    using namespace nvcuda;
    wmma::fragment<wmma::accumulator, 16, 16, 16, float> acc[4];
    #pragma unroll
    for (int n = 0; n < 4; n++) wmma::fill_fragment(acc[n], 0.0f);

    const int m0 = warp * 16;
    #pragma unroll
    for (int kc = 0; kc < 8; kc++) {
        const int k0 = kc * 16;
        wmma::fragment<wmma::matrix_a, 16, 16, 16, __half, wmma::row_major> af;
        wmma::load_matrix_sync(af, sa + m0 * LDA + k0, LDA);
        #pragma unroll
        for (int n = 0; n < 4; n++) {
            wmma::fragment<wmma::matrix_b, 16, 16, 16, __half, wmma::row_major> bf;
            wmma::load_matrix_sync(bf, sb + k0 * LDB + n * 16, LDB);
            wmma::mma_sync(acc[n], af, bf, acc[n]);
        }
    }

    #pragma unroll
    for (int n = 0; n < 4; n++)
        wmma::store_matrix_sync(so + m0 * LDO + n * 16, acc[n], LDO, wmma::mem_row_major);

    {   // row norms: 2 threads per row (warp-local rows; no cross-warp hazard yet)
        int row = t >> 1, halfsel = t & 1;
        float s = 0.f;
        #pragma unroll
        for (int c = 0; c < 32; c++) {
            int col = halfsel * 32 + c;
            float v = so[row * LDO + col] + sbias[col];
            s = fmaf(v, v, s);
        }
        s += __shfl_xor_sync(0xffffffffu, s, 1);
        if (halfsel == 0) snorm[row] = 1.0f / fmaxf(sqrtf(s), 1e-12f);
    }
    __syncthreads();

    #pragma unroll
    for (int it = 0; it < 8; it++) {
        int i = t + 128 * it;            // 0..1023 float4 units over 64x64
        int row = i >> 4;
        int c4 = (i & 15) << 2;
        int node = node0 + row;
        if (node >= N_NODES) continue;
        float sc = snorm[row];
        float v0 = (so[row * LDO + c4 + 0] + sbias[c4 + 0]) * sc;
        float v1 = (so[row * LDO + c4 + 1] + sbias[c4 + 1]) * sc;
        float v2 = (so[row * LDO + c4 + 2] + sbias[c4 + 2]) * sc;
        float v3 = (so[row * LDO + c4 + 3] + sbias[c4 + 3]) * sc;
        if (apply_bn) {
            v0 = fmaxf(fmaf(v0, ssc[c4 + 0], sbs[c4 + 0]), 0.f);
            v1 = fmaxf(fmaf(v1, ssc[c4 + 1], sbs[c4 + 1]), 0.f);
            v2 = fmaxf(fmaf(v2, ssc[c4 + 2], sbs[c4 + 2]), 0.f);
            v3 = fmaxf(fmaf(v3, ssc[c4 + 3], sbs[c4 + 3]), 0.f);
        }
        if (write32) {
            *(float4*)&out32[node * C + c4] = make_float4(v0, v1, v2, v3);
        } else {
            __half2 q[2];
            q[0] = __floats2half2_rn(v0, v1);
            q[1] = __floats2half2_rn(v2, v3);
            *(uint2*)&out16[node * C + c4] = *(uint2*)q;
        }
    }
}

// ---------------- host ----------------
extern "C" void kernel_launch(void* const* d_in, const int* in_sizes, int n_in,
                              void* d_out, int out_size) {
    const float* x    = (const float*)d_in[0];
    const int*   esrc = (const int*)d_in[1];
    const int*   edst = (const int*)d_in[2];

    int iw1[3], iw2[3], ib2[3], ibn[2][4];
    if (n_in > 6 && in_sizes[6] == 4096) {
        for (int l = 0; l < 3; l++) { iw1[l] = 3 + 3 * l; iw2[l] = 4 + 3 * l; ib2[l] = 5 + 3 * l; }
        for (int l = 0; l < 2; l++)
            for (int j = 0; j < 4; j++) ibn[l][j] = 12 + 4 * l + j;
    } else {
        iw1[0] = 3;  iw2[0] = 4;  ib2[0] = 5;
        for (int j = 0; j < 4; j++) ibn[0][j] = 6 + j;
        iw1[1] = 10; iw2[1] = 11; ib2[1] = 12;
        for (int j = 0; j < 4; j++) ibn[1][j] = 13 + j;
        iw1[2] = 17; iw2[2] = 18; ib2[2] = 19;
    }

    __half *h16, *agg16, *wc;
    float *ideg;
    int *cnt, *row_ptr, *cursor, *csr_src;
    cudaGetSymbolAddress((void**)&h16,     g_h16);
    cudaGetSymbolAddress((void**)&agg16,   g_agg16);
    cudaGetSymbolAddress((void**)&wc,      g_wc);
    cudaGetSymbolAddress((void**)&ideg,    g_ideg);
    cudaGetSymbolAddress((void**)&cnt,     g_cnt);
    cudaGetSymbolAddress((void**)&row_ptr, g_row_ptr);
    cudaGetSymbolAddress((void**)&cursor,  g_cursor);
    cudaGetSymbolAddress((void**)&csr_src, g_csr_src);

    const int NB_NODE = (N_NODES + 255) / 256;
    const int NB_EDGE = (N_EDGES + 255) / 256;
    const int NB_FILL = (N_EDGES / 8 + 255) / 256;
    const int NB_PREP = NB_CVT_K + (3 * 8192 + 255) / 256;
    const int NB_AGG  = (N_NODES + 31) / 32;
    const int NB_MMA  = (N_NODES + 63) / 64;

    // ---- launches 1-5: CSR build + prep (so launch #6 = agg, for ncu -s 5) ----
    zero_cnt_kernel<<<NB_NODE, 256>>>(cnt);
    hist_kernel<<<NB_EDGE, 256>>>(edst, cnt);
    scan_kernel<<<1, 1024>>>(cnt, row_ptr, cursor, ideg);
    fill_kernel<<<NB_FILL, 256>>>(esrc, edst, cursor, csr_src);
    prep_kernel<<<NB_PREP, 256>>>(x, h16,
                                  (const float*)d_in[iw1[0]], (const float*)d_in[iw2[0]],
                                  (const float*)d_in[iw1[1]], (const float*)d_in[iw2[1]],
                                  (const float*)d_in[iw1[2]], (const float*)d_in[iw2[2]],
                                  wc);

    for (int l = 0; l < 3; l++) {
        agg_f16_kernel<<<NB_AGG, 256>>>(h16, row_ptr, csr_src, ideg, agg16);
        int has_bn = (l < 2);
        // in-place h16 update is safe: each block reads its own 64 rows to smem
        // before writing them back.
        sage_wmma_kernel<<<NB_MMA, 128>>>(
            h16, agg16, wc + l * 128 * 64,
            (const float*)d_in[ib2[l]],
            has_bn ? (const float*)d_in[ibn[l][0]] : (const float*)d_in[ib2[l]],
            has_bn ? (const float*)d_in[ibn[l][1]] : (const float*)d_in[ib2[l]],
            has_bn ? (const float*)d_in[ibn[l][2]] : (const float*)d_in[ib2[l]],
            has_bn ? (const float*)d_in[ibn[l][3]] : (const float*)d_in[ib2[l]],
            (float*)d_out, h16, has_bn, (l == 2) ? 1 : 0);
    }
}

// round 12
// speedup vs baseline: 1.6845x; 1.0540x over previous
#include <cuda_runtime.h>
#include <cuda_fp16.h>
#include <mma.h>

#define N_NODES 100000
#define N_EDGES 1600000
#define C 64
#define LDA 136   // halves; 272B row stride
#define LDB 72    // halves; 144B row stride
#define LDO 68    // floats; 272B row stride (aliases A region)
#define MMA_ROWS 128
#define MMA_THREADS 256

// dynamic smem layout for wmma kernel
#define SA_BYTES (MMA_ROWS * LDA * 2)          // 34816
#define SB_BYTES (128 * LDB * 2)               // 18432
#define SMEM_WMMA (SA_BYTES + SB_BYTES + (64 * 3 + MMA_ROWS) * 4)  // +1280 -> 54528

// ---------------- scratch (device globals: no allocations allowed) ----------------
__device__ __align__(16) __half g_h16[N_NODES * C];    // fp16 current features
__device__ __align__(16) __half g_agg16[N_NODES * C];  // fp16 neighbor mean
__device__ __align__(16) __half g_wc[3][128 * 64];     // per-layer combined [W1;W2]^T fp16
__device__ float g_ideg[N_NODES];
__device__ int g_cnt[N_NODES];
__device__ int g_row_ptr[N_NODES + 1];
__device__ int g_cursor[N_NODES];
__device__ int g_csr_src[N_EDGES];

// ---------------- CSR build ----------------
__global__ void zero_cnt_kernel(int* __restrict__ cnt) {
    int i = blockIdx.x * blockDim.x + threadIdx.x;
    if (i < N_NODES) cnt[i] = 0;
}

__global__ void hist_kernel(const int* __restrict__ dst, int* __restrict__ cnt) {
    int e = blockIdx.x * blockDim.x + threadIdx.x;
    if (e < N_EDGES) atomicAdd(&cnt[dst[e]], 1);
}

__global__ __launch_bounds__(1024) void scan_kernel(
    const int* __restrict__ cnt, int* __restrict__ row_ptr,
    int* __restrict__ cursor, float* __restrict__ ideg)
{
    __shared__ int part[1024];
    const int t = threadIdx.x;
    const int CH = (N_NODES + 1023) / 1024;   // 98
    int begin = t * CH;
    int end = begin + CH; if (end > N_NODES) end = N_NODES;
    int s = 0;
    for (int i = begin; i < end; i++) s += cnt[i];
    part[t] = s;
    __syncthreads();
    for (int off = 1; off < 1024; off <<= 1) {
        int u = (t >= off) ? part[t - off] : 0;
        __syncthreads();
        part[t] += u;
        __syncthreads();
    }
    int run = part[t] - s;
    for (int i = begin; i < end; i++) {
        int c = cnt[i];
        row_ptr[i] = run;
        cursor[i]  = run;
        ideg[i] = 1.0f / (float)(c > 1 ? c : 1);
        run += c;
    }
    if (t == 1023) row_ptr[N_NODES] = part[1023];
}

// 4 edges per thread (best measured variant)
__global__ void fill_kernel(const int* __restrict__ src, const int* __restrict__ dst,
                            int* __restrict__ cursor, int* __restrict__ csr_src) {
    int base = (blockIdx.x * blockDim.x + threadIdx.x) * 4;
    #pragma unroll
    for (int u = 0; u < 4; u++) {
        int e = base + u;
        if (e < N_EDGES) {
            int pos = atomicAdd(&cursor[dst[e]], 1);
            csr_src[pos] = src[e];
        }
    }
}

// ---------------- prep: x -> fp16 shadow AND all 3 layers' combined weights ----
#define NB_CVT_K ((N_NODES * C / 4 + 255) / 256)
__global__ void prep_kernel(const float* __restrict__ x, __half* __restrict__ h16,
                            const float* __restrict__ w1_0, const float* __restrict__ w2_0,
                            const float* __restrict__ w1_1, const float* __restrict__ w2_1,
                            const float* __restrict__ w1_2, const float* __restrict__ w2_2,
                            __half* __restrict__ wc) {
    int b = blockIdx.x;
    if (b < NB_CVT_K) {
        int i = b * 256 + threadIdx.x;
        if (i < N_NODES * C / 4) {
            float4 v = ((const float4*)x)[i];
            __half2 p[2];
            p[0] = __floats2half2_rn(v.x, v.y);
            p[1] = __floats2half2_rn(v.z, v.w);
            ((uint2*)h16)[i] = *(uint2*)p;
        }
    } else {
        int i = (b - NB_CVT_K) * 256 + threadIdx.x;   // 0..24575 = 3 layers x 8192
        if (i < 3 * 8192) {
            int l = i >> 13;
            int r = i & 8191;
            int k = r >> 6, n = r & 63;
            const float* w1 = (l == 0) ? w1_0 : (l == 1) ? w1_1 : w1_2;
            const float* w2 = (l == 0) ? w2_0 : (l == 1) ? w2_1 : w2_2;
            float v = (k < 64) ? w1[n * 64 + k] : w2[n * 64 + (k - 64)];
            wc[l * 8192 + k * 64 + n] = __float2half(v);
        }
    }
}

// ---------------- aggregation: agg16[n] = mean_{s in N(n)} h16[s] ----------------
// 8 lanes/node, 16B/lane. 8 row-loads in flight per lane per iteration.
__device__ __forceinline__ void accum8(float* a, uint4 r) {
    __half2* p = (__half2*)&r;
    #pragma unroll
    for (int i = 0; i < 4; i++) {
        float2 f = __half22float2(p[i]);
        a[2 * i]     += f.x;
        a[2 * i + 1] += f.y;
    }
}

__global__ __launch_bounds__(256) void agg_f16_kernel(
    const __half* __restrict__ h16,
    const int* __restrict__ row_ptr, const int* __restrict__ csr_src,
    const float* __restrict__ ideg, __half* __restrict__ agg16)
{
    const int t = threadIdx.x;
    const int node = blockIdx.x * 32 + (t >> 3);
    const int c8 = (t & 7) << 3;
    if (node >= N_NODES) return;

    const int beg = __ldg(&row_ptr[node]);
    const int end = __ldg(&row_ptr[node + 1]);

    float a0[8], a1[8], a2[8], a3[8];
    #pragma unroll
    for (int i = 0; i < 8; i++) { a0[i] = a1[i] = a2[i] = a3[i] = 0.f; }

    int j = beg;
    for (; j + 7 < end; j += 8) {
        int s0 = __ldg(&csr_src[j + 0]);
        int s1 = __ldg(&csr_src[j + 1]);
        int s2 = __ldg(&csr_src[j + 2]);
        int s3 = __ldg(&csr_src[j + 3]);
        int s4 = __ldg(&csr_src[j + 4]);
        int s5 = __ldg(&csr_src[j + 5]);
        int s6 = __ldg(&csr_src[j + 6]);
        int s7 = __ldg(&csr_src[j + 7]);
        uint4 r0 = *(const uint4*)(h16 + s0 * C + c8);
        uint4 r1 = *(const uint4*)(h16 + s1 * C + c8);
        uint4 r2 = *(const uint4*)(h16 + s2 * C + c8);
        uint4 r3 = *(const uint4*)(h16 + s3 * C + c8);
        uint4 r4 = *(const uint4*)(h16 + s4 * C + c8);
        uint4 r5 = *(const uint4*)(h16 + s5 * C + c8);
        uint4 r6 = *(const uint4*)(h16 + s6 * C + c8);
        uint4 r7 = *(const uint4*)(h16 + s7 * C + c8);
        accum8(a0, r0); accum8(a1, r1); accum8(a2, r2); accum8(a3, r3);
        accum8(a0, r4); accum8(a1, r5); accum8(a2, r6); accum8(a3, r7);
    }
    for (; j + 3 < end; j += 4) {
        int s0 = __ldg(&csr_src[j + 0]);
        int s1 = __ldg(&csr_src[j + 1]);
        int s2 = __ldg(&csr_src[j + 2]);
        int s3 = __ldg(&csr_src[j + 3]);
        uint4 r0 = *(const uint4*)(h16 + s0 * C + c8);
        uint4 r1 = *(const uint4*)(h16 + s1 * C + c8);
        uint4 r2 = *(const uint4*)(h16 + s2 * C + c8);
        uint4 r3 = *(const uint4*)(h16 + s3 * C + c8);
        accum8(a0, r0); accum8(a1, r1); accum8(a2, r2); accum8(a3, r3);
    }
    for (; j < end; j++) {
        int s0 = __ldg(&csr_src[j]);
        uint4 r0 = *(const uint4*)(h16 + s0 * C + c8);
        accum8(a0, r0);
    }

    const float id = __ldg(&ideg[node]);
    __half2 outp[4];
    #pragma unroll
    for (int i = 0; i < 4; i++) {
        float x0 = (a0[2 * i]     + a1[2 * i]     + a2[2 * i]     + a3[2 * i])     * id;
        float x1 = (a0[2 * i + 1] + a1[2 * i + 1] + a2[2 * i + 1] + a3[2 * i + 1]) * id;
        outp[i] = __floats2half2_rn(x0, x1);
    }
    *(uint4*)(agg16 + node * C + c8) = *(uint4*)outp;
}

// ---------------- tensor-core fused layer (WMMA, dynamic smem, 128 rows/block) ----
// out[m, 0:64] = rownorm( [h16 | agg16][m, 0:128] @ wc + b ) [-> BN -> ReLU]
// 256 threads (8 warps), 128 rows/block. Warp w -> rows 16w..16w+15.
// ~54.5KB dynamic smem -> ~4 blocks/SM -> 1024 threads/SM (vs 1 block/128 thr before).
__global__ __launch_bounds__(MMA_THREADS) void sage_wmma_kernel(
    const __half* __restrict__ h16, const __half* __restrict__ agg16,
    const __half* __restrict__ wc,
    const float* __restrict__ b2,
    const float* __restrict__ bn_g, const float* __restrict__ bn_b,
    const float* __restrict__ bn_m, const float* __restrict__ bn_v,
    float* __restrict__ out32, __half* __restrict__ out16,
    int apply_bn, int write32)
{
    extern __shared__ __align__(16) char dsmem[];
    __half* sa = (__half*)dsmem;                         // [128][LDA]; aliased as so[128][LDO] floats
    __half* sb = (__half*)(dsmem + SA_BYTES);            // [128][LDB]
    float* sbias = (float*)(dsmem + SA_BYTES + SB_BYTES);
    float* ssc   = sbias + 64;
    float* sbs   = ssc + 64;
    float* snorm = sbs + 64;                             // [128]
    float* so = reinterpret_cast<float*>(sa);

    const int t = threadIdx.x;
    const int warp = t >> 5;
    const int node0 = blockIdx.x * MMA_ROWS;

    for (int i = t; i < 1024; i += MMA_THREADS) {        // B: wc[128][64] -> sb
        int k = i >> 3, c8 = (i & 7) << 3;
        *(uint4*)&sb[k * LDB + c8] = *(const uint4*)&wc[k * 64 + c8];
    }
    if (t < 64) {
        sbias[t] = b2[t];
        if (apply_bn) {
            float sc = bn_g[t] * rsqrtf(bn_v[t] + 1e-5f);
            ssc[t] = sc;
            sbs[t] = bn_b[t] - bn_m[t] * sc;
        }
    }
    for (int i = t; i < MMA_ROWS * 16; i += MMA_THREADS) {   // A: [h16 | agg16]
        int row = i >> 4, c8 = (i & 15) << 3;
        int node = node0 + row;
        uint4 v = make_uint4(0, 0, 0, 0);
        if (node < N_NODES)
            v = (c8 < 64) ? *(const uint4*)&h16[node * C + c8]
                          : *(const uint4*)&agg16[node * C + c8 - 64];
        *(uint4*)&sa[row * LDA + c8] = v;
    }
    __syncthreads();

    using namespace nvcuda;
    wmma::fragment<wmma::accumulator, 16, 16, 16, float> acc[4];
    #pragma unroll
    for (int n = 0; n < 4; n++) wmma::fill_fragment(acc[n], 0.0f);

    const int m0 = warp * 16;
    #pragma unroll
    for (int kc = 0; kc < 8; kc++) {
        const int k0 = kc * 16;
        wmma::fragment<wmma::matrix_a, 16, 16, 16, __half, wmma::row_major> af;
        wmma::load_matrix_sync(af, sa + m0 * LDA + k0, LDA);
        #pragma unroll
        for (int n = 0; n < 4; n++) {
            wmma::fragment<wmma::matrix_b, 16, 16, 16, __half, wmma::row_major> bf;
            wmma::load_matrix_sync(bf, sb + k0 * LDB + n * 16, LDB);
            wmma::mma_sync(acc[n], af, bf, acc[n]);
        }
    }

    // stage accumulators over the (consumed, warp-local) A rows
    #pragma unroll
    for (int n = 0; n < 4; n++)
        wmma::store_matrix_sync(so + m0 * LDO + n * 16, acc[n], LDO, wmma::mem_row_major);

    {   // row norms: 2 threads per row (rows warp-local; no cross-warp hazard)
        int row = t >> 1, halfsel = t & 1;
        float s = 0.f;
        #pragma unroll
        for (int c = 0; c < 32; c++) {
            int col = halfsel * 32 + c;
            float v = so[row * LDO + col] + sbias[col];
            s = fmaf(v, v, s);
        }
        s += __shfl_xor_sync(0xffffffffu, s, 1);
        if (halfsel == 0) snorm[row] = 1.0f / fmaxf(sqrtf(s), 1e-12f);
    }
    __syncthreads();

    #pragma unroll
    for (int it = 0; it < 8; it++) {
        int i = t + MMA_THREADS * it;    // 0..2047 float4 units over 128x64
        int row = i >> 4;
        int c4 = (i & 15) << 2;
        int node = node0 + row;
        if (node >= N_NODES) continue;
        float sc = snorm[row];
        float v0 = (so[row * LDO + c4 + 0] + sbias[c4 + 0]) * sc;
        float v1 = (so[row * LDO + c4 + 1] + sbias[c4 + 1]) * sc;
        float v2 = (so[row * LDO + c4 + 2] + sbias[c4 + 2]) * sc;
        float v3 = (so[row * LDO + c4 + 3] + sbias[c4 + 3]) * sc;
        if (apply_bn) {
            v0 = fmaxf(fmaf(v0, ssc[c4 + 0], sbs[c4 + 0]), 0.f);
            v1 = fmaxf(fmaf(v1, ssc[c4 + 1], sbs[c4 + 1]), 0.f);
            v2 = fmaxf(fmaf(v2, ssc[c4 + 2], sbs[c4 + 2]), 0.f);
            v3 = fmaxf(fmaf(v3, ssc[c4 + 3], sbs[c4 + 3]), 0.f);
        }
        if (write32) {
            *(float4*)&out32[node * C + c4] = make_float4(v0, v1, v2, v3);
        } else {
            __half2 q[2];
            q[0] = __floats2half2_rn(v0, v1);
            q[1] = __floats2half2_rn(v2, v3);
            *(uint2*)&out16[node * C + c4] = *(uint2*)q;
        }
    }
}

// ---------------- host ----------------
extern "C" void kernel_launch(void* const* d_in, const int* in_sizes, int n_in,
                              void* d_out, int out_size) {
    const float* x    = (const float*)d_in[0];
    const int*   esrc = (const int*)d_in[1];
    const int*   edst = (const int*)d_in[2];

    int iw1[3], iw2[3], ib2[3], ibn[2][4];
    if (n_in > 6 && in_sizes[6] == 4096) {
        for (int l = 0; l < 3; l++) { iw1[l] = 3 + 3 * l; iw2[l] = 4 + 3 * l; ib2[l] = 5 + 3 * l; }
        for (int l = 0; l < 2; l++)
            for (int j = 0; j < 4; j++) ibn[l][j] = 12 + 4 * l + j;
    } else {
        iw1[0] = 3;  iw2[0] = 4;  ib2[0] = 5;
        for (int j = 0; j < 4; j++) ibn[0][j] = 6 + j;
        iw1[1] = 10; iw2[1] = 11; ib2[1] = 12;
        for (int j = 0; j < 4; j++) ibn[1][j] = 13 + j;
        iw1[2] = 17; iw2[2] = 18; ib2[2] = 19;
    }

    __half *h16, *agg16, *wc;
    float *ideg;
    int *cnt, *row_ptr, *cursor, *csr_src;
    cudaGetSymbolAddress((void**)&h16,     g_h16);
    cudaGetSymbolAddress((void**)&agg16,   g_agg16);
    cudaGetSymbolAddress((void**)&wc,      g_wc);
    cudaGetSymbolAddress((void**)&ideg,    g_ideg);
    cudaGetSymbolAddress((void**)&cnt,     g_cnt);
    cudaGetSymbolAddress((void**)&row_ptr, g_row_ptr);
    cudaGetSymbolAddress((void**)&cursor,  g_cursor);
    cudaGetSymbolAddress((void**)&csr_src, g_csr_src);

    cudaFuncSetAttribute(sage_wmma_kernel,
                         cudaFuncAttributeMaxDynamicSharedMemorySize, SMEM_WMMA);

    const int NB_NODE = (N_NODES + 255) / 256;
    const int NB_EDGE = (N_EDGES + 255) / 256;
    const int NB_FILL = (N_EDGES / 4 + 255) / 256;
    const int NB_PREP = NB_CVT_K + (3 * 8192 + 255) / 256;
    const int NB_AGG  = (N_NODES + 31) / 32;
    const int NB_MMA  = (N_NODES + MMA_ROWS - 1) / MMA_ROWS;

    // ---- CSR build + prep ----
    zero_cnt_kernel<<<NB_NODE, 256>>>(cnt);
    hist_kernel<<<NB_EDGE, 256>>>(edst, cnt);
    scan_kernel<<<1, 1024>>>(cnt, row_ptr, cursor, ideg);
    fill_kernel<<<NB_FILL, 256>>>(esrc, edst, cursor, csr_src);
    prep_kernel<<<NB_PREP, 256>>>(x, h16,
                                  (const float*)d_in[iw1[0]], (const float*)d_in[iw2[0]],
                                  (const float*)d_in[iw1[1]], (const float*)d_in[iw2[1]],
                                  (const float*)d_in[iw1[2]], (const float*)d_in[iw2[2]],
                                  wc);

    for (int l = 0; l < 3; l++) {
        agg_f16_kernel<<<NB_AGG, 256>>>(h16, row_ptr, csr_src, ideg, agg16);
        int has_bn = (l < 2);
        // in-place h16 update is safe: each block reads its own rows to smem
        // before writing them back.
        sage_wmma_kernel<<<NB_MMA, MMA_THREADS, SMEM_WMMA>>>(
            h16, agg16, wc + l * 128 * 64,
            (const float*)d_in[ib2[l]],
            has_bn ? (const float*)d_in[ibn[l][0]] : (const float*)d_in[ib2[l]],
            has_bn ? (const float*)d_in[ibn[l][1]] : (const float*)d_in[ib2[l]],
            has_bn ? (const float*)d_in[ibn[l][2]] : (const float*)d_in[ib2[l]],
            has_bn ? (const float*)d_in[ibn[l][3]] : (const float*)d_in[ib2[l]],
            (float*)d_out, h16, has_bn, (l == 2) ? 1 : 0);
    }
}

// round 13
// speedup vs baseline: 1.6968x; 1.0073x over previous
#include <cuda_runtime.h>
#include <cuda_fp16.h>
#include <mma.h>

#define N_NODES 100000
#define N_EDGES 1600000
#define C 64
#define LDA 136   // halves; 272B row stride
#define LDB 72    // halves; 144B row stride
#define LDO 68    // floats; 272B row stride (aliases A region)
#define MMA_ROWS 128
#define MMA_THREADS 256

// dynamic smem layout for wmma kernel
#define SA_BYTES (MMA_ROWS * LDA * 2)          // 34816
#define SB_BYTES (128 * LDB * 2)               // 18432
#define SMEM_WMMA (SA_BYTES + SB_BYTES + (64 * 3 + MMA_ROWS) * 4)  // -> 54528

// ---------------- scratch (device globals: no allocations allowed) ----------------
// NOTE: g_cnt relies on zero-initialization at module load AND is re-zeroed by the
// trailing cleanup launch each invocation, so every kernel_launch call sees cnt==0.
__device__ __align__(16) __half g_h16[N_NODES * C];    // fp16 current features
__device__ __align__(16) __half g_agg16[N_NODES * C];  // fp16 neighbor mean
__device__ __align__(16) __half g_wc[3][128 * 64];     // per-layer combined [W1;W2]^T fp16
__device__ float g_ideg[N_NODES];
__device__ int g_cnt[N_NODES];
__device__ int g_row_ptr[N_NODES + 1];
__device__ int g_cursor[N_NODES];
__device__ int g_csr_src[N_EDGES];

// ---------------- launch 1: hist + x->fp16 + weight prep (independent block ranges) ----
#define NB_EDGE_K ((N_EDGES + 255) / 256)                 // 6250
#define NB_CVT_K  ((N_NODES * C / 4 + 255) / 256)         // 6250
#define NB_W_K    ((3 * 8192 + 255) / 256)                // 96
__global__ void hist_prep_kernel(const int* __restrict__ dst, int* __restrict__ cnt,
                                 const float* __restrict__ x, __half* __restrict__ h16,
                                 const float* __restrict__ w1_0, const float* __restrict__ w2_0,
                                 const float* __restrict__ w1_1, const float* __restrict__ w2_1,
                                 const float* __restrict__ w1_2, const float* __restrict__ w2_2,
                                 __half* __restrict__ wc) {
    int b = blockIdx.x;
    if (b < NB_EDGE_K) {
        int e = b * 256 + threadIdx.x;
        if (e < N_EDGES) atomicAdd(&cnt[dst[e]], 1);
    } else if (b < NB_EDGE_K + NB_CVT_K) {
        int i = (b - NB_EDGE_K) * 256 + threadIdx.x;
        if (i < N_NODES * C / 4) {
            float4 v = ((const float4*)x)[i];
            __half2 p[2];
            p[0] = __floats2half2_rn(v.x, v.y);
            p[1] = __floats2half2_rn(v.z, v.w);
            ((uint2*)h16)[i] = *(uint2*)p;
        }
    } else {
        int i = (b - NB_EDGE_K - NB_CVT_K) * 256 + threadIdx.x;   // 0..24575
        if (i < 3 * 8192) {
            int l = i >> 13;
            int r = i & 8191;
            int k = r >> 6, n = r & 63;
            const float* w1 = (l == 0) ? w1_0 : (l == 1) ? w1_1 : w1_2;
            const float* w2 = (l == 0) ? w2_0 : (l == 1) ? w2_1 : w2_2;
            float v = (k < 64) ? w1[n * 64 + k] : w2[n * 64 + (k - 64)];
            wc[l * 8192 + k * 64 + n] = __float2half(v);
        }
    }
}

// ---------------- launch 2: single-block scan of counts -> row_ptr, cursor, ideg ----
__global__ __launch_bounds__(1024) void scan_kernel(
    const int* __restrict__ cnt, int* __restrict__ row_ptr,
    int* __restrict__ cursor, float* __restrict__ ideg)
{
    __shared__ int part[1024];
    const int t = threadIdx.x;
    const int CH = (N_NODES + 1023) / 1024;   // 98
    int begin = t * CH;
    int end = begin + CH; if (end > N_NODES) end = N_NODES;
    int s = 0;
    for (int i = begin; i < end; i++) s += cnt[i];
    part[t] = s;
    __syncthreads();
    for (int off = 1; off < 1024; off <<= 1) {
        int u = (t >= off) ? part[t - off] : 0;
        __syncthreads();
        part[t] += u;
        __syncthreads();
    }
    int run = part[t] - s;
    for (int i = begin; i < end; i++) {
        int c = cnt[i];
        row_ptr[i] = run;
        cursor[i]  = run;
        ideg[i] = 1.0f / (float)(c > 1 ? c : 1);
        run += c;
    }
    if (t == 1023) row_ptr[N_NODES] = part[1023];
}

// ---------------- launch 3: CSR fill (4 edges/thread, measured best) ----
__global__ void fill_kernel(const int* __restrict__ src, const int* __restrict__ dst,
                            int* __restrict__ cursor, int* __restrict__ csr_src) {
    int base = (blockIdx.x * blockDim.x + threadIdx.x) * 4;
    #pragma unroll
    for (int u = 0; u < 4; u++) {
        int e = base + u;
        if (e < N_EDGES) {
            int pos = atomicAdd(&cursor[dst[e]], 1);
            csr_src[pos] = src[e];
        }
    }
}

// ---------------- trailing cleanup: restore cnt==0 for next invocation ----
__global__ void cleanup_cnt_kernel(int* __restrict__ cnt) {
    int i = blockIdx.x * blockDim.x + threadIdx.x;
    if (i < N_NODES) cnt[i] = 0;
}

// ---------------- aggregation: agg16[n] = mean_{s in N(n)} h16[s] (UNCHANGED from R12) ----
__device__ __forceinline__ void accum8(float* a, uint4 r) {
    __half2* p = (__half2*)&r;
    #pragma unroll
    for (int i = 0; i < 4; i++) {
        float2 f = __half22float2(p[i]);
        a[2 * i]     += f.x;
        a[2 * i + 1] += f.y;
    }
}

__global__ __launch_bounds__(256) void agg_f16_kernel(
    const __half* __restrict__ h16,
    const int* __restrict__ row_ptr, const int* __restrict__ csr_src,
    const float* __restrict__ ideg, __half* __restrict__ agg16)
{
    const int t = threadIdx.x;
    const int node = blockIdx.x * 32 + (t >> 3);
    const int c8 = (t & 7) << 3;
    if (node >= N_NODES) return;

    const int beg = __ldg(&row_ptr[node]);
    const int end = __ldg(&row_ptr[node + 1]);

    float a0[8], a1[8], a2[8], a3[8];
    #pragma unroll
    for (int i = 0; i < 8; i++) { a0[i] = a1[i] = a2[i] = a3[i] = 0.f; }

    int j = beg;
    for (; j + 7 < end; j += 8) {
        int s0 = __ldg(&csr_src[j + 0]);
        int s1 = __ldg(&csr_src[j + 1]);
        int s2 = __ldg(&csr_src[j + 2]);
        int s3 = __ldg(&csr_src[j + 3]);
        int s4 = __ldg(&csr_src[j + 4]);
        int s5 = __ldg(&csr_src[j + 5]);
        int s6 = __ldg(&csr_src[j + 6]);
        int s7 = __ldg(&csr_src[j + 7]);
        uint4 r0 = *(const uint4*)(h16 + s0 * C + c8);
        uint4 r1 = *(const uint4*)(h16 + s1 * C + c8);
        uint4 r2 = *(const uint4*)(h16 + s2 * C + c8);
        uint4 r3 = *(const uint4*)(h16 + s3 * C + c8);
        uint4 r4 = *(const uint4*)(h16 + s4 * C + c8);
        uint4 r5 = *(const uint4*)(h16 + s5 * C + c8);
        uint4 r6 = *(const uint4*)(h16 + s6 * C + c8);
        uint4 r7 = *(const uint4*)(h16 + s7 * C + c8);
        accum8(a0, r0); accum8(a1, r1); accum8(a2, r2); accum8(a3, r3);
        accum8(a0, r4); accum8(a1, r5); accum8(a2, r6); accum8(a3, r7);
    }
    for (; j + 3 < end; j += 4) {
        int s0 = __ldg(&csr_src[j + 0]);
        int s1 = __ldg(&csr_src[j + 1]);
        int s2 = __ldg(&csr_src[j + 2]);
        int s3 = __ldg(&csr_src[j + 3]);
        uint4 r0 = *(const uint4*)(h16 + s0 * C + c8);
        uint4 r1 = *(const uint4*)(h16 + s1 * C + c8);
        uint4 r2 = *(const uint4*)(h16 + s2 * C + c8);
        uint4 r3 = *(const uint4*)(h16 + s3 * C + c8);
        accum8(a0, r0); accum8(a1, r1); accum8(a2, r2); accum8(a3, r3);
    }
    for (; j < end; j++) {
        int s0 = __ldg(&csr_src[j]);
        uint4 r0 = *(const uint4*)(h16 + s0 * C + c8);
        accum8(a0, r0);
    }

    const float id = __ldg(&ideg[node]);
    __half2 outp[4];
    #pragma unroll
    for (int i = 0; i < 4; i++) {
        float x0 = (a0[2 * i]     + a1[2 * i]     + a2[2 * i]     + a3[2 * i])     * id;
        float x1 = (a0[2 * i + 1] + a1[2 * i + 1] + a2[2 * i + 1] + a3[2 * i + 1]) * id;
        outp[i] = __floats2half2_rn(x0, x1);
    }
    *(uint4*)(agg16 + node * C + c8) = *(uint4*)outp;
}

// ---------------- tensor-core fused layer (WMMA; UNCHANGED from R12) ----------------
__global__ __launch_bounds__(MMA_THREADS) void sage_wmma_kernel(
    const __half* __restrict__ h16, const __half* __restrict__ agg16,
    const __half* __restrict__ wc,
    const float* __restrict__ b2,
    const float* __restrict__ bn_g, const float* __restrict__ bn_b,
    const float* __restrict__ bn_m, const float* __restrict__ bn_v,
    float* __restrict__ out32, __half* __restrict__ out16,
    int apply_bn, int write32)
{
    extern __shared__ __align__(16) char dsmem[];
    __half* sa = (__half*)dsmem;                         // [128][LDA]; aliased as so[128][LDO]
    __half* sb = (__half*)(dsmem + SA_BYTES);            // [128][LDB]
    float* sbias = (float*)(dsmem + SA_BYTES + SB_BYTES);
    float* ssc   = sbias + 64;
    float* sbs   = ssc + 64;
    float* snorm = sbs + 64;                             // [128]
    float* so = reinterpret_cast<float*>(sa);

    const int t = threadIdx.x;
    const int warp = t >> 5;
    const int node0 = blockIdx.x * MMA_ROWS;

    for (int i = t; i < 1024; i += MMA_THREADS) {        // B: wc[128][64] -> sb
        int k = i >> 3, c8 = (i & 7) << 3;
        *(uint4*)&sb[k * LDB + c8] = *(const uint4*)&wc[k * 64 + c8];
    }
    if (t < 64) {
        sbias[t] = b2[t];
        if (apply_bn) {
            float sc = bn_g[t] * rsqrtf(bn_v[t] + 1e-5f);
            ssc[t] = sc;
            sbs[t] = bn_b[t] - bn_m[t] * sc;
        }
    }
    for (int i = t; i < MMA_ROWS * 16; i += MMA_THREADS) {   // A: [h16 | agg16]
        int row = i >> 4, c8 = (i & 15) << 3;
        int node = node0 + row;
        uint4 v = make_uint4(0, 0, 0, 0);
        if (node < N_NODES)
            v = (c8 < 64) ? *(const uint4*)&h16[node * C + c8]
                          : *(const uint4*)&agg16[node * C + c8 - 64];
        *(uint4*)&sa[row * LDA + c8] = v;
    }
    __syncthreads();

    using namespace nvcuda;
    wmma::fragment<wmma::accumulator, 16, 16, 16, float> acc[4];
    #pragma unroll
    for (int n = 0; n < 4; n++) wmma::fill_fragment(acc[n], 0.0f);

    const int m0 = warp * 16;
    #pragma unroll
    for (int kc = 0; kc < 8; kc++) {
        const int k0 = kc * 16;
        wmma::fragment<wmma::matrix_a, 16, 16, 16, __half, wmma::row_major> af;
        wmma::load_matrix_sync(af, sa + m0 * LDA + k0, LDA);
        #pragma unroll
        for (int n = 0; n < 4; n++) {
            wmma::fragment<wmma::matrix_b, 16, 16, 16, __half, wmma::row_major> bf;
            wmma::load_matrix_sync(bf, sb + k0 * LDB + n * 16, LDB);
            wmma::mma_sync(acc[n], af, bf, acc[n]);
        }
    }

    #pragma unroll
    for (int n = 0; n < 4; n++)
        wmma::store_matrix_sync(so + m0 * LDO + n * 16, acc[n], LDO, wmma::mem_row_major);

    {   // row norms: 2 threads per row (rows warp-local; no cross-warp hazard)
        int row = t >> 1, halfsel = t & 1;
        float s = 0.f;
        #pragma unroll
        for (int c = 0; c < 32; c++) {
            int col = halfsel * 32 + c;
            float v = so[row * LDO + col] + sbias[col];
            s = fmaf(v, v, s);
        }
        s += __shfl_xor_sync(0xffffffffu, s, 1);
        if (halfsel == 0) snorm[row] = 1.0f / fmaxf(sqrtf(s), 1e-12f);
    }
    __syncthreads();

    #pragma unroll
    for (int it = 0; it < 8; it++) {
        int i = t + MMA_THREADS * it;    // 0..2047 float4 units over 128x64
        int row = i >> 4;
        int c4 = (i & 15) << 2;
        int node = node0 + row;
        if (node >= N_NODES) continue;
        float sc = snorm[row];
        float v0 = (so[row * LDO + c4 + 0] + sbias[c4 + 0]) * sc;
        float v1 = (so[row * LDO + c4 + 1] + sbias[c4 + 1]) * sc;
        float v2 = (so[row * LDO + c4 + 2] + sbias[c4 + 2]) * sc;
        float v3 = (so[row * LDO + c4 + 3] + sbias[c4 + 3]) * sc;
        if (apply_bn) {
            v0 = fmaxf(fmaf(v0, ssc[c4 + 0], sbs[c4 + 0]), 0.f);
            v1 = fmaxf(fmaf(v1, ssc[c4 + 1], sbs[c4 + 1]), 0.f);
            v2 = fmaxf(fmaf(v2, ssc[c4 + 2], sbs[c4 + 2]), 0.f);
            v3 = fmaxf(fmaf(v3, ssc[c4 + 3], sbs[c4 + 3]), 0.f);
        }
        if (write32) {
            *(float4*)&out32[node * C + c4] = make_float4(v0, v1, v2, v3);
        } else {
            __half2 q[2];
            q[0] = __floats2half2_rn(v0, v1);
            q[1] = __floats2half2_rn(v2, v3);
            *(uint2*)&out16[node * C + c4] = *(uint2*)q;
        }
    }
}

// ---------------- host ----------------
extern "C" void kernel_launch(void* const* d_in, const int* in_sizes, int n_in,
                              void* d_out, int out_size) {
    const float* x    = (const float*)d_in[0];
    const int*   esrc = (const int*)d_in[1];
    const int*   edst = (const int*)d_in[2];

    int iw1[3], iw2[3], ib2[3], ibn[2][4];
    if (n_in > 6 && in_sizes[6] == 4096) {
        for (int l = 0; l < 3; l++) { iw1[l] = 3 + 3 * l; iw2[l] = 4 + 3 * l; ib2[l] = 5 + 3 * l; }
        for (int l = 0; l < 2; l++)
            for (int j = 0; j < 4; j++) ibn[l][j] = 12 + 4 * l + j;
    } else {
        iw1[0] = 3;  iw2[0] = 4;  ib2[0] = 5;
        for (int j = 0; j < 4; j++) ibn[0][j] = 6 + j;
        iw1[1] = 10; iw2[1] = 11; ib2[1] = 12;
        for (int j = 0; j < 4; j++) ibn[1][j] = 13 + j;
        iw1[2] = 17; iw2[2] = 18; ib2[2] = 19;
    }

    __half *h16, *agg16, *wc;
    float *ideg;
    int *cnt, *row_ptr, *cursor, *csr_src;
    cudaGetSymbolAddress((void**)&h16,     g_h16);
    cudaGetSymbolAddress((void**)&agg16,   g_agg16);
    cudaGetSymbolAddress((void**)&wc,      g_wc);
    cudaGetSymbolAddress((void**)&ideg,    g_ideg);
    cudaGetSymbolAddress((void**)&cnt,     g_cnt);
    cudaGetSymbolAddress((void**)&row_ptr, g_row_ptr);
    cudaGetSymbolAddress((void**)&cursor,  g_cursor);
    cudaGetSymbolAddress((void**)&csr_src, g_csr_src);

    cudaFuncSetAttribute(sage_wmma_kernel,
                         cudaFuncAttributeMaxDynamicSharedMemorySize, SMEM_WMMA);

    const int NB_HP   = NB_EDGE_K + NB_CVT_K + NB_W_K;
    const int NB_FILL = (N_EDGES / 4 + 255) / 256;
    const int NB_AGG  = (N_NODES + 31) / 32;
    const int NB_MMA  = (N_NODES + MMA_ROWS - 1) / MMA_ROWS;
    const int NB_NODE = (N_NODES + 255) / 256;

    // launch 1: hist (cnt==0 guaranteed: static init + trailing cleanup) + x->fp16 + wconv
    hist_prep_kernel<<<NB_HP, 256>>>(edst, cnt, x, h16,
                                     (const float*)d_in[iw1[0]], (const float*)d_in[iw2[0]],
                                     (const float*)d_in[iw1[1]], (const float*)d_in[iw2[1]],
                                     (const float*)d_in[iw1[2]], (const float*)d_in[iw2[2]],
                                     wc);
    // launch 2: scan
    scan_kernel<<<1, 1024>>>(cnt, row_ptr, cursor, ideg);
    // launch 3: fill
    fill_kernel<<<NB_FILL, 256>>>(esrc, edst, cursor, csr_src);

    // launches 4..9: 3 x (agg, wmma). launch 4 == agg layer 0 -> profiled by ncu.
    for (int l = 0; l < 3; l++) {
        agg_f16_kernel<<<NB_AGG, 256>>>(h16, row_ptr, csr_src, ideg, agg16);
        int has_bn = (l < 2);
        sage_wmma_kernel<<<NB_MMA, MMA_THREADS, SMEM_WMMA>>>(
            h16, agg16, wc + l * 128 * 64,
            (const float*)d_in[ib2[l]],
            has_bn ? (const float*)d_in[ibn[l][0]] : (const float*)d_in[ib2[l]],
            has_bn ? (const float*)d_in[ibn[l][1]] : (const float*)d_in[ib2[l]],
            has_bn ? (const float*)d_in[ibn[l][2]] : (const float*)d_in[ib2[l]],
            has_bn ? (const float*)d_in[ibn[l][3]] : (const float*)d_in[ib2[l]],
            (float*)d_out, h16, has_bn, (l == 2) ? 1 : 0);
    }

    // launch 10: restore cnt == 0 for the next invocation (determinism across replays)
    cleanup_cnt_kernel<<<NB_NODE, 256>>>(cnt);
}